// round 7
// baseline (speedup 1.0000x reference)
#include <cuda_runtime.h>
#include <cuda_bf16.h>
#include <stdint.h>

#define NLAYER 15
#define NSLOT  6               // ring of per-layer 32KB weight slots

// int8-split weight image: per layer 32KB.
// entry e = kt*8 + nt2 (kt=0..3 k32-tiles, nt2=0..7 n16-chunks):
//   [hi frags 512B][lo frags 512B], frag = uint4 per lane:
//   (b0 ntile 2nt2, b1 ntile 2nt2, b0 ntile 2nt2+1, b1 ntile 2nt2+1)
//   b0 = int8x4 {Wq[k][n] : k = kt*32 + tig*4 + 0..3}, b1: k+16; n = ntile*8 + g
__device__ __align__(128) unsigned char g_wimg[NLAYER * 32768];
__device__ float g_wsc[NLAYER * 128];   // per-column scale dw = colmax/32512

// ---------------- smem layout ----------------
#define SO_FULL   0                    // 6 mbarriers x 8B
#define SO_CNT    64                   // 15 uint32 counters
#define SO_W1     256                  // 256 floats
#define SO_B1     1280                 // 128 floats
#define SO_W17    1792                 // 128 floats
#define SO_BIAS   2304                 // 15*128 floats
#define SO_WSC    9984                 // 15*128 floats
#define SO_WBUF   18432                // 1024-aligned; 6 x 32768 ring
#define SMEM_TOTAL (18432 + NSLOT*32768)   // 215040 B

// ---------------- helpers ----------------
__device__ __forceinline__ uint32_t smem_u32(const void* p) {
    uint32_t a;
    asm("{ .reg .u64 t; cvta.to.shared.u64 t, %1; cvt.u32.u64 %0, t; }" : "=r"(a) : "l"(p));
    return a;
}
__device__ __forceinline__ void mbar_init(uint32_t mbar, uint32_t cnt) {
    asm volatile("mbarrier.init.shared.b64 [%0], %1;" :: "r"(mbar), "r"(cnt) : "memory");
}
__device__ __forceinline__ void mbar_expect_tx(uint32_t mbar, uint32_t bytes) {
    asm volatile("mbarrier.arrive.expect_tx.shared.b64 _, [%0], %1;" :: "r"(mbar), "r"(bytes) : "memory");
}
__device__ __forceinline__ void mbar_wait(uint32_t mbar, uint32_t parity) {
    asm volatile(
        "{\n\t.reg .pred P;\n\t"
        "WL_%=:\n\t"
        "mbarrier.try_wait.parity.acquire.cta.shared::cta.b64 P, [%0], %1, 0x989680;\n\t"
        "@P bra WD_%=;\n\t"
        "bra.uni WL_%=;\n\t"
        "WD_%=:\n\t}"
        :: "r"(mbar), "r"(parity) : "memory");
}
__device__ __forceinline__ void bulk_g2s(uint32_t dst, const void* src, uint32_t bytes, uint32_t mbar) {
    asm volatile("cp.async.bulk.shared::cta.global.mbarrier::complete_tx::bytes [%0], [%1], %2, [%3];"
                 :: "r"(dst), "l"(src), "r"(bytes), "r"(mbar) : "memory");
}
__device__ __forceinline__ uint32_t atom_inc_acqrel(uint32_t addr) {
    uint32_t old;
    asm volatile("atom.acq_rel.cta.shared::cta.add.u32 %0, [%1], 1;"
                 : "=r"(old) : "r"(addr) : "memory");
    return old;
}
__device__ __forceinline__ uint4 lds128(uint32_t addr) {
    uint4 v;
    asm volatile("ld.shared.v4.b32 {%0,%1,%2,%3}, [%4];"
                 : "=r"(v.x), "=r"(v.y), "=r"(v.z), "=r"(v.w) : "r"(addr));
    return v;
}
// int8 MMA m16n8k32: 2x MACs per instruction vs bf16 k16
__device__ __forceinline__ void imma16832(int* d, const uint32_t* a, uint32_t b0, uint32_t b1) {
    asm volatile(
        "mma.sync.aligned.m16n8k32.row.col.s32.s8.s8.s32 "
        "{%0,%1,%2,%3}, {%4,%5,%6,%7}, {%8,%9}, {%0,%1,%2,%3};"
        : "+r"(d[0]), "+r"(d[1]), "+r"(d[2]), "+r"(d[3])
        : "r"(a[0]), "r"(a[1]), "r"(a[2]), "r"(a[3]), "r"(b0), "r"(b1));
}
__device__ __forceinline__ uint32_t pack4(int b0, int b1, int b2, int b3) {
    return (uint32_t)(b0 & 255) | ((uint32_t)(b1 & 255) << 8)
         | ((uint32_t)(b2 & 255) << 16) | ((uint32_t)(b3 & 255) << 24);
}

// ---------------- prep kernels ----------------
__global__ void prep_scales(const float* __restrict__ Ws) {
    int idx = blockIdx.x * blockDim.x + threadIdx.x;
    if (idx >= NLAYER * 128) return;
    int layer = idx >> 7, n = idx & 127;
    const float* W = Ws + layer * 16384 + n;
    float m = 0.f;
    for (int k = 0; k < 128; k++) m = fmaxf(m, fabsf(W[k * 128]));
    g_wsc[idx] = fmaxf(m, 1e-20f) * (1.0f / 32512.0f);
}

__global__ void prep_weights(const float* __restrict__ Ws) {
    int idx = blockIdx.x * blockDim.x + threadIdx.x;
    if (idx >= NLAYER * 32 * 32) return;
    int lane  = idx & 31;
    int e     = (idx >> 5) & 31;    // kt*8 + nt2
    int layer = idx >> 10;
    int kt  = e >> 3;
    int nt2 = e & 7;
    int g   = lane >> 2;
    int tig = lane & 3;
    const float* W = Ws + layer * 16384;

    uint32_t hw[4], lw[4];
#pragma unroll
    for (int r = 0; r < 4; r++) {       // r: (ntile sel<<1)|b-reg
        int n = nt2 * 16 + (r >> 1) * 8 + g;
        int kb = kt * 32 + (r & 1) * 16 + tig * 4;
        float invw = 1.0f / g_wsc[layer * 128 + n];
        int h[4], l[4];
#pragma unroll
        for (int j = 0; j < 4; j++) {
            int q = __float2int_rn(W[(kb + j) * 128 + n] * invw);   // [-32512, 32512]
            h[j] = (q + 128) >> 8;           // [-127, 127]
            l[j] = q - (h[j] << 8);          // [-128, 127]
        }
        hw[r] = pack4(h[0], h[1], h[2], h[3]);
        lw[r] = pack4(l[0], l[1], l[2], l[3]);
    }
    size_t off = (size_t)layer * 32768u + (size_t)e * 1024u + (size_t)lane * 16u;
    *reinterpret_cast<uint4*>(&g_wimg[off])        = make_uint4(hw[0], hw[1], hw[2], hw[3]);
    *reinterpret_cast<uint4*>(&g_wimg[off + 512u]) = make_uint4(lw[0], lw[1], lw[2], lw[3]);
}

// ---------------- quantize epilogue: v[16][4] -> int8-split A fragments ------
// v[nt][0,1] = row g cols nt*8+2tig{,+1}; v[nt][2,3] = row g+8 same cols.
// Produces Ahi/Alo[kt][r]: r0 = row g k=32kt+4tig+0..3, r1 = row g+8 same,
// r2/r3 = k+16. Cross-lane repack via SHFL.IDX within each 4-lane tig group.
__device__ __forceinline__ void quant_epilogue(
    float (&v)[16][4], int lane,
    uint32_t (&Ahi)[4][4], uint32_t (&Alo)[4][4],
    float& da_g, float& da_g8)
{
    int tig = lane & 3;
    // relu + per-row max
    float mg = 0.f, mg8 = 0.f;
#pragma unroll
    for (int nt = 0; nt < 16; nt++) {
        v[nt][0] = fmaxf(v[nt][0], 0.f);
        v[nt][1] = fmaxf(v[nt][1], 0.f);
        v[nt][2] = fmaxf(v[nt][2], 0.f);
        v[nt][3] = fmaxf(v[nt][3], 0.f);
        mg  = fmaxf(mg,  fmaxf(v[nt][0], v[nt][1]));
        mg8 = fmaxf(mg8, fmaxf(v[nt][2], v[nt][3]));
    }
    mg  = fmaxf(mg,  __shfl_xor_sync(0xFFFFFFFFu, mg, 1));
    mg  = fmaxf(mg,  __shfl_xor_sync(0xFFFFFFFFu, mg, 2));
    mg8 = fmaxf(mg8, __shfl_xor_sync(0xFFFFFFFFu, mg8, 1));
    mg8 = fmaxf(mg8, __shfl_xor_sync(0xFFFFFFFFu, mg8, 2));
    mg = fmaxf(mg, 1e-20f);
    mg8 = fmaxf(mg8, 1e-20f);
    float ig  = 32512.0f / mg;
    float ig8 = 32512.0f / mg8;
    da_g  = mg  * (1.0f / 32512.0f);
    da_g8 = mg8 * (1.0f / 32512.0f);

    uint32_t ph[16], pl[16];
#pragma unroll
    for (int nt = 0; nt < 16; nt++) {
        int q0 = __float2int_rn(v[nt][0] * ig);
        int q1 = __float2int_rn(v[nt][1] * ig);
        int q2 = __float2int_rn(v[nt][2] * ig8);
        int q3 = __float2int_rn(v[nt][3] * ig8);
        int h0 = (q0 + 128) >> 8, l0 = q0 - (h0 << 8);
        int h1 = (q1 + 128) >> 8, l1 = q1 - (h1 << 8);
        int h2 = (q2 + 128) >> 8, l2 = q2 - (h2 << 8);
        int h3 = (q3 + 128) >> 8, l3 = q3 - (h3 << 8);
        ph[nt] = pack4(h0, h1, h2, h3);
        pl[nt] = pack4(l0, l1, l2, l3);
    }

    int sA = (lane & ~3) | ((tig & 1) << 1);   // owner of k-bytes 0,1
    int sB = sA + 1;                            // owner of k-bytes 2,3
    bool up = (tig >> 1) != 0;                  // which nt within the pair
#pragma unroll
    for (int kt = 0; kt < 4; kt++) {
        // hi
        uint32_t q0A = __shfl_sync(0xFFFFFFFFu, ph[4 * kt + 0], sA);
        uint32_t q0B = __shfl_sync(0xFFFFFFFFu, ph[4 * kt + 0], sB);
        uint32_t q1A = __shfl_sync(0xFFFFFFFFu, ph[4 * kt + 1], sA);
        uint32_t q1B = __shfl_sync(0xFFFFFFFFu, ph[4 * kt + 1], sB);
        uint32_t q2A = __shfl_sync(0xFFFFFFFFu, ph[4 * kt + 2], sA);
        uint32_t q2B = __shfl_sync(0xFFFFFFFFu, ph[4 * kt + 2], sB);
        uint32_t q3A = __shfl_sync(0xFFFFFFFFu, ph[4 * kt + 3], sA);
        uint32_t q3B = __shfl_sync(0xFFFFFFFFu, ph[4 * kt + 3], sB);
        uint32_t xA = up ? q1A : q0A, xB = up ? q1B : q0B;
        uint32_t yA = up ? q3A : q2A, yB = up ? q3B : q2B;
        Ahi[kt][0] = __byte_perm(xA, xB, 0x5410);
        Ahi[kt][1] = __byte_perm(xA, xB, 0x7632);
        Ahi[kt][2] = __byte_perm(yA, yB, 0x5410);
        Ahi[kt][3] = __byte_perm(yA, yB, 0x7632);
        // lo
        q0A = __shfl_sync(0xFFFFFFFFu, pl[4 * kt + 0], sA);
        q0B = __shfl_sync(0xFFFFFFFFu, pl[4 * kt + 0], sB);
        q1A = __shfl_sync(0xFFFFFFFFu, pl[4 * kt + 1], sA);
        q1B = __shfl_sync(0xFFFFFFFFu, pl[4 * kt + 1], sB);
        q2A = __shfl_sync(0xFFFFFFFFu, pl[4 * kt + 2], sA);
        q2B = __shfl_sync(0xFFFFFFFFu, pl[4 * kt + 2], sB);
        q3A = __shfl_sync(0xFFFFFFFFu, pl[4 * kt + 3], sA);
        q3B = __shfl_sync(0xFFFFFFFFu, pl[4 * kt + 3], sB);
        xA = up ? q1A : q0A; xB = up ? q1B : q0B;
        yA = up ? q3A : q2A; yB = up ? q3B : q2B;
        Alo[kt][0] = __byte_perm(xA, xB, 0x5410);
        Alo[kt][1] = __byte_perm(xA, xB, 0x7632);
        Alo[kt][2] = __byte_perm(yA, yB, 0x5410);
        Alo[kt][3] = __byte_perm(yA, yB, 0x7632);
    }
}

// ---------------- main fused MLP kernel ------------------------------------
__global__ void __launch_bounds__(256, 1)
mlp_kernel(const float* __restrict__ x, const float* __restrict__ W1,
           const float* __restrict__ b1, const float* __restrict__ bs,
           const float* __restrict__ W17, const float* __restrict__ b17,
           float* __restrict__ out) {
    extern __shared__ __align__(1024) unsigned char smem[];
    uint32_t sb = smem_u32(smem);
    int tid  = threadIdx.x;
    int wid  = tid >> 5;
    int lane = tid & 31;
    int g    = lane >> 2;
    int tig  = lane & 3;

    float* sW1  = reinterpret_cast<float*>(smem + SO_W1);
    float* sB1  = reinterpret_cast<float*>(smem + SO_B1);
    float* sW17 = reinterpret_cast<float*>(smem + SO_W17);
    float* sBias= reinterpret_cast<float*>(smem + SO_BIAS);
    float* sWsc = reinterpret_cast<float*>(smem + SO_WSC);

    if (tid < NSLOT) mbar_init(sb + SO_FULL + 8u * tid, 1);
    if (tid < 256) sW1[tid] = W1[tid];
    if (tid < 128) { sB1[tid] = b1[tid]; sW17[tid] = W17[tid]; }
    if (tid < NLAYER) reinterpret_cast<uint32_t*>(smem + SO_CNT)[tid] = 0;
    for (int idx = tid; idx < NLAYER * 128; idx += 256) {
        sBias[idx] = bs[idx];
        sWsc[idx]  = g_wsc[idx];
    }
    __syncthreads();

    if (tid == 0) {
#pragma unroll
        for (int j = 0; j < NSLOT; j++) {
            mbar_expect_tx(sb + SO_FULL + 8u * j, 32768);
            bulk_g2s(sb + SO_WBUF + 32768u * j, &g_wimg[(size_t)j * 32768u], 32768,
                     sb + SO_FULL + 8u * j);
        }
    }

    float b17v = b17[0];

    // ---- fc1: v = x @ W1 + b1 (relu applied inside quant_epilogue) ----
    size_t p0 = (size_t)blockIdx.x * 128 + (size_t)(wid * 16 + g);
    float2 xa = reinterpret_cast<const float2*>(x)[p0];
    float2 xb = reinterpret_cast<const float2*>(x)[p0 + 8];

    float v[16][4];
#pragma unroll
    for (int nt = 0; nt < 16; nt++) {
        int c = nt * 8 + tig * 2;
        v[nt][0] = fmaf(xa.x, sW1[c],     fmaf(xa.y, sW1[128 + c],     sB1[c]));
        v[nt][1] = fmaf(xa.x, sW1[c + 1], fmaf(xa.y, sW1[128 + c + 1], sB1[c + 1]));
        v[nt][2] = fmaf(xb.x, sW1[c],     fmaf(xb.y, sW1[128 + c],     sB1[c]));
        v[nt][3] = fmaf(xb.x, sW1[c + 1], fmaf(xb.y, sW1[128 + c + 1], sB1[c + 1]));
    }

    uint32_t Ahi[4][4], Alo[4][4];
    float da_g, da_g8;
    quant_epilogue(v, lane, Ahi, Alo, da_g, da_g8);

    // seed warp-phase stagger
    if (wid) __nanosleep((unsigned)(wid * 250));

    for (int i = 0; i < NLAYER; i++) {
        int slot = i % NSLOT;
        mbar_wait(sb + SO_FULL + 8u * slot, (uint32_t)((i / NSLOT) & 1));
        uint32_t wb = sb + SO_WBUF + (uint32_t)slot * 32768u + (uint32_t)lane * 16u;

        const float* bi = sBias + i * 128 + tig * 2;
        const float* sc = sWsc  + i * 128 + tig * 2;

#pragma unroll
        for (int nt2 = 0; nt2 < 8; nt2++) {
            int Dhh[2][4] = {{0,0,0,0},{0,0,0,0}};
            int Dcr[2][4] = {{0,0,0,0},{0,0,0,0}};
#pragma unroll
            for (int kt = 0; kt < 4; kt++) {
                uint32_t off = (uint32_t)((kt * 8 + nt2) * 1024);
                uint4 whi = lds128(wb + off);
                uint4 wlo = lds128(wb + off + 512u);
                imma16832(Dhh[0], Ahi[kt], whi.x, whi.y);
                imma16832(Dhh[1], Ahi[kt], whi.z, whi.w);
                imma16832(Dcr[0], Ahi[kt], wlo.x, wlo.y);
                imma16832(Dcr[1], Ahi[kt], wlo.z, wlo.w);
                imma16832(Dcr[0], Alo[kt], whi.x, whi.y);
                imma16832(Dcr[1], Alo[kt], whi.z, whi.w);
            }
            // merge: v = (Dhh*65536 + Dcr*256) * da * dw + bias  (exact pow2 scales)
#pragma unroll
            for (int t = 0; t < 2; t++) {
                int nt = 2 * nt2 + t;
                float2 bb = *reinterpret_cast<const float2*>(bi + nt * 8);
                float2 ww = *reinterpret_cast<const float2*>(sc + nt * 8);
                float t0 = fmaf((float)Dhh[t][0], 65536.f, (float)Dcr[t][0] * 256.f);
                float t1 = fmaf((float)Dhh[t][1], 65536.f, (float)Dcr[t][1] * 256.f);
                float t2 = fmaf((float)Dhh[t][2], 65536.f, (float)Dcr[t][2] * 256.f);
                float t3 = fmaf((float)Dhh[t][3], 65536.f, (float)Dcr[t][3] * 256.f);
                v[nt][0] = fmaf(t0, da_g  * ww.x, bb.x);
                v[nt][1] = fmaf(t1, da_g  * ww.y, bb.y);
                v[nt][2] = fmaf(t2, da_g8 * ww.x, bb.x);
                v[nt][3] = fmaf(t3, da_g8 * ww.y, bb.y);
            }
        }

        // ring: last warp through layer i refills slot with layer i+6
        if (lane == 0) {
            uint32_t old = atom_inc_acqrel(sb + SO_CNT + 4u * (uint32_t)i);
            if (old == 7 && i + NSLOT < NLAYER) {
                asm volatile("fence.proxy.async.shared::cta;" ::: "memory");
                uint32_t fb = sb + SO_FULL + 8u * (uint32_t)slot;
                mbar_expect_tx(fb, 32768);
                bulk_g2s(sb + SO_WBUF + (uint32_t)slot * 32768u,
                         &g_wimg[(size_t)(i + NSLOT) * 32768u], 32768, fb);
            }
        }

        if (i < NLAYER - 1) {
            quant_epilogue(v, lane, Ahi, Alo, da_g, da_g8);
        } else {
            // fc17: relu + dot with W17, shfl reduce over 4-lane col groups
            const float* w7 = sW17 + tig * 2;
            float s0 = 0.f, s1 = 0.f;
#pragma unroll
            for (int nt = 0; nt < 16; nt++) {
                float2 w2 = *reinterpret_cast<const float2*>(w7 + nt * 8);
                float v0 = fmaxf(v[nt][0], 0.f);
                float v1 = fmaxf(v[nt][1], 0.f);
                float v2 = fmaxf(v[nt][2], 0.f);
                float v3 = fmaxf(v[nt][3], 0.f);
                s0 = fmaf(v0, w2.x, fmaf(v1, w2.y, s0));
                s1 = fmaf(v2, w2.x, fmaf(v3, w2.y, s1));
            }
            s0 += __shfl_xor_sync(0xFFFFFFFFu, s0, 1);
            s0 += __shfl_xor_sync(0xFFFFFFFFu, s0, 2);
            s1 += __shfl_xor_sync(0xFFFFFFFFu, s1, 1);
            s1 += __shfl_xor_sync(0xFFFFFFFFu, s1, 2);
            if (tig == 0) {
                out[p0]     = s0 + b17v;
                out[p0 + 8] = s1 + b17v;
            }
        }
    }
}

// ---------------- launch ----------------
extern "C" void kernel_launch(void* const* d_in, const int* in_sizes, int n_in,
                              void* d_out, int out_size) {
    const float* x   = (const float*)d_in[0];
    const float* W1  = (const float*)d_in[1];
    const float* b1  = (const float*)d_in[2];
    const float* Ws  = (const float*)d_in[3];
    const float* bs  = (const float*)d_in[4];
    const float* W17 = (const float*)d_in[5];
    const float* b17 = (const float*)d_in[6];
    float* out = (float*)d_out;

    cudaFuncSetAttribute(mlp_kernel, cudaFuncAttributeMaxDynamicSharedMemorySize, SMEM_TOTAL);

    int npts = in_sizes[0] / 2;
    int nblk = npts / 128;

    prep_scales<<<(NLAYER * 128 + 255) / 256, 256>>>(Ws);
    prep_weights<<<(NLAYER * 32 * 32 + 255) / 256, 256>>>(Ws);
    mlp_kernel<<<nblk, 256, SMEM_TOTAL>>>(x, W1, b1, bs, W17, b17, out);
}

// round 8
// speedup vs baseline: 8.9330x; 8.9330x over previous
#include <cuda_runtime.h>
#include <cuda_fp16.h>
#include <stdint.h>

#define NLAYER 15
#define NSLOT  6               // ring of per-layer 32KB weight slots

// fp16 fragment-ordered weights: per layer 32KB.
// entry e = kt*8 + nt2 (kt=0..7 k16-tiles, nt2=0..7 n16-chunks): uint4 per lane:
//   (b0 ntile 2nt2, b1 ntile 2nt2, b0 ntile 2nt2+1, b1 ntile 2nt2+1)
//   b0 = fp16x2 {W[k0][n], W[k0+1][n]}, k0 = kt*16+tig*2, b1: k0+8; n = ntile*8+g
__device__ __align__(128) unsigned char g_wimg[NLAYER * 32768];

// ---------------- smem layout ----------------
#define SO_FULL   0                    // 6 mbarriers x 8B
#define SO_CNT    64                   // 15 uint32 counters
#define SO_W1     256                  // 256 floats
#define SO_B1     1280                 // 128 floats
#define SO_W17    1792                 // 128 floats
#define SO_BIAS   2304                 // 15*128 floats
#define SO_WBUF   10240                // 1024-aligned; 6 x 32768 ring
#define SMEM_TOTAL (10240 + NSLOT*32768)   // 206848 B

// ---------------- helpers ----------------
__device__ __forceinline__ uint32_t smem_u32(const void* p) {
    uint32_t a;
    asm("{ .reg .u64 t; cvta.to.shared.u64 t, %1; cvt.u32.u64 %0, t; }" : "=r"(a) : "l"(p));
    return a;
}
__device__ __forceinline__ void mbar_init(uint32_t mbar, uint32_t cnt) {
    asm volatile("mbarrier.init.shared.b64 [%0], %1;" :: "r"(mbar), "r"(cnt) : "memory");
}
__device__ __forceinline__ void mbar_expect_tx(uint32_t mbar, uint32_t bytes) {
    asm volatile("mbarrier.arrive.expect_tx.shared.b64 _, [%0], %1;" :: "r"(mbar), "r"(bytes) : "memory");
}
__device__ __forceinline__ void mbar_wait(uint32_t mbar, uint32_t parity) {
    asm volatile(
        "{\n\t.reg .pred P;\n\t"
        "WL_%=:\n\t"
        "mbarrier.try_wait.parity.acquire.cta.shared::cta.b64 P, [%0], %1, 0x989680;\n\t"
        "@P bra WD_%=;\n\t"
        "bra.uni WL_%=;\n\t"
        "WD_%=:\n\t}"
        :: "r"(mbar), "r"(parity) : "memory");
}
__device__ __forceinline__ void bulk_g2s(uint32_t dst, const void* src, uint32_t bytes, uint32_t mbar) {
    asm volatile("cp.async.bulk.shared::cta.global.mbarrier::complete_tx::bytes [%0], [%1], %2, [%3];"
                 :: "r"(dst), "l"(src), "r"(bytes), "r"(mbar) : "memory");
}
__device__ __forceinline__ uint32_t atom_inc_acqrel(uint32_t addr) {
    uint32_t old;
    asm volatile("atom.acq_rel.cta.shared::cta.add.u32 %0, [%1], 1;"
                 : "=r"(old) : "r"(addr) : "memory");
    return old;
}
__device__ __forceinline__ uint4 lds128(uint32_t addr) {
    uint4 v;
    asm volatile("ld.shared.v4.b32 {%0,%1,%2,%3}, [%4];"
                 : "=r"(v.x), "=r"(v.y), "=r"(v.z), "=r"(v.w) : "r"(addr));
    return v;
}
// fp16 MMA m16n8k16, fp32 accumulate (same HMMA pipe/rate as bf16)
__device__ __forceinline__ void mma16816(float* d, const uint32_t* a, uint32_t b0, uint32_t b1) {
    asm volatile(
        "mma.sync.aligned.m16n8k16.row.col.f32.f16.f16.f32 "
        "{%0,%1,%2,%3}, {%4,%5,%6,%7}, {%8,%9}, {%0,%1,%2,%3};"
        : "+f"(d[0]), "+f"(d[1]), "+f"(d[2]), "+f"(d[3])
        : "r"(a[0]), "r"(a[1]), "r"(a[2]), "r"(a[3]), "r"(b0), "r"(b1));
}
__device__ __forceinline__ uint32_t packh2(float a, float b) {
    __half2 h = __float22half2_rn(make_float2(a, b));
    return *reinterpret_cast<uint32_t*>(&h);
}

// ---------------- prep: weights -> fp16 per-lane fragment layout ----------------
__global__ void prep_weights(const float* __restrict__ Ws) {
    int idx = blockIdx.x * blockDim.x + threadIdx.x;
    if (idx >= NLAYER * 64 * 32) return;
    int lane  = idx & 31;
    int e     = (idx >> 5) & 63;   // kt*8 + nt2
    int layer = idx >> 11;
    int kt  = e >> 3;
    int nt2 = e & 7;
    int tig = lane & 3;
    int g   = lane >> 2;
    int k0 = kt * 16 + tig * 2;
    const float* W = Ws + layer * 16384;

    auto pk = [&](int k, int n) -> uint32_t {
        return packh2(W[k * 128 + n], W[(k + 1) * 128 + n]);
    };
    int n0 = nt2 * 16 + g;
    uint4 r;
    r.x = pk(k0,     n0);
    r.y = pk(k0 + 8, n0);
    r.z = pk(k0,     n0 + 8);
    r.w = pk(k0 + 8, n0 + 8);
    *reinterpret_cast<uint4*>(&g_wimg[(size_t)layer * 32768u + (size_t)e * 512u
                                      + (size_t)lane * 16u]) = r;
}

// ---------------- main fused MLP kernel ------------------------------------
__global__ void __launch_bounds__(256, 1)
mlp_kernel(const float* __restrict__ x, const float* __restrict__ W1,
           const float* __restrict__ b1, const float* __restrict__ bs,
           const float* __restrict__ W17, const float* __restrict__ b17,
           float* __restrict__ out) {
    extern __shared__ __align__(1024) unsigned char smem[];
    uint32_t sb = smem_u32(smem);
    int tid  = threadIdx.x;
    int wid  = tid >> 5;
    int lane = tid & 31;
    int g    = lane >> 2;   // row group within warp tile
    int tig  = lane & 3;    // thread-in-group (column pair selector)

    float* sW1  = reinterpret_cast<float*>(smem + SO_W1);
    float* sB1  = reinterpret_cast<float*>(smem + SO_B1);
    float* sW17 = reinterpret_cast<float*>(smem + SO_W17);
    float* sBias= reinterpret_cast<float*>(smem + SO_BIAS);

    if (tid < NSLOT) mbar_init(sb + SO_FULL + 8u * tid, 1);
    if (tid < 256) sW1[tid] = W1[tid];
    if (tid < 128) { sB1[tid] = b1[tid]; sW17[tid] = W17[tid]; }
    if (tid < NLAYER) reinterpret_cast<uint32_t*>(smem + SO_CNT)[tid] = 0;
    for (int idx = tid; idx < NLAYER * 128; idx += 256) sBias[idx] = bs[idx];
    __syncthreads();

    if (tid == 0) {
#pragma unroll
        for (int j = 0; j < NSLOT; j++) {
            mbar_expect_tx(sb + SO_FULL + 8u * j, 32768);
            bulk_g2s(sb + SO_WBUF + 32768u * j, &g_wimg[(size_t)j * 32768u], 32768,
                     sb + SO_FULL + 8u * j);
        }
    }

    float b17v = b17[0];

    // ---- fc1: h1 = relu(x @ W1 + b1) -> fp16 A fragments in registers ----
    size_t p0 = (size_t)blockIdx.x * 128 + (size_t)(wid * 16 + g);
    float2 xa = reinterpret_cast<const float2*>(x)[p0];       // row g
    float2 xb = reinterpret_cast<const float2*>(x)[p0 + 8];   // row g+8

    uint32_t A[8][4];
#pragma unroll
    for (int kt = 0; kt < 8; kt++) {
        int c = kt * 16 + tig * 2;
        float va0 = fmaxf(fmaf(xa.x, sW1[c],     fmaf(xa.y, sW1[128 + c],     sB1[c])),     0.f);
        float va1 = fmaxf(fmaf(xa.x, sW1[c + 1], fmaf(xa.y, sW1[128 + c + 1], sB1[c + 1])), 0.f);
        float vb0 = fmaxf(fmaf(xb.x, sW1[c],     fmaf(xb.y, sW1[128 + c],     sB1[c])),     0.f);
        float vb1 = fmaxf(fmaf(xb.x, sW1[c + 1], fmaf(xb.y, sW1[128 + c + 1], sB1[c + 1])), 0.f);
        float va2 = fmaxf(fmaf(xa.x, sW1[c + 8], fmaf(xa.y, sW1[128 + c + 8], sB1[c + 8])), 0.f);
        float va3 = fmaxf(fmaf(xa.x, sW1[c + 9], fmaf(xa.y, sW1[128 + c + 9], sB1[c + 9])), 0.f);
        float vb2 = fmaxf(fmaf(xb.x, sW1[c + 8], fmaf(xb.y, sW1[128 + c + 8], sB1[c + 8])), 0.f);
        float vb3 = fmaxf(fmaf(xb.x, sW1[c + 9], fmaf(xb.y, sW1[128 + c + 9], sB1[c + 9])), 0.f);
        A[kt][0] = packh2(va0, va1);
        A[kt][1] = packh2(vb0, vb1);
        A[kt][2] = packh2(va2, va3);
        A[kt][3] = packh2(vb2, vb3);
    }

    // seed warp-phase stagger so epilogues of some warps overlap MMAs of others
    if (wid) __nanosleep((unsigned)(wid * 250));

    float D[16][4];

    for (int i = 0; i < NLAYER; i++) {
        // init D with this layer's bias (D = bias + A@W)
        const float* bi = sBias + i * 128 + tig * 2;
#pragma unroll
        for (int nt = 0; nt < 16; nt++) {
            float2 bb = *reinterpret_cast<const float2*>(bi + nt * 8);
            D[nt][0] = bb.x; D[nt][1] = bb.y; D[nt][2] = bb.x; D[nt][3] = bb.y;
        }

        int slot = i % NSLOT;
        mbar_wait(sb + SO_FULL + 8u * slot, (uint32_t)((i / NSLOT) & 1));
        uint32_t wb = sb + SO_WBUF + (uint32_t)slot * 32768u + (uint32_t)lane * 16u;

        // 1-pass fp16 GEMM: 128 MMAs, 64 LDS.128
#pragma unroll
        for (int kt = 0; kt < 8; kt++) {
#pragma unroll
            for (int nt2 = 0; nt2 < 8; nt2++) {
                uint4 w = lds128(wb + (uint32_t)((kt * 8 + nt2) * 512));
                mma16816(D[2 * nt2],     A[kt], w.x, w.y);
                mma16816(D[2 * nt2 + 1], A[kt], w.z, w.w);
            }
        }

        // ring: last warp through layer i refills slot with layer i+6
        if (lane == 0) {
            uint32_t old = atom_inc_acqrel(sb + SO_CNT + 4u * (uint32_t)i);
            if (old == 7 && i + NSLOT < NLAYER) {
                asm volatile("fence.proxy.async.shared::cta;" ::: "memory");
                uint32_t fb = sb + SO_FULL + 8u * (uint32_t)slot;
                mbar_expect_tx(fb, 32768);
                bulk_g2s(sb + SO_WBUF + (uint32_t)slot * 32768u,
                         &g_wimg[(size_t)(i + NSLOT) * 32768u], 32768, fb);
            }
        }

        if (i < NLAYER - 1) {
            // epilogue: relu + fp16 pack, register-local D -> next A fragments
#pragma unroll
            for (int nt = 0; nt < 16; nt++) {
                float v0 = fmaxf(D[nt][0], 0.f);
                float v1 = fmaxf(D[nt][1], 0.f);
                float v2 = fmaxf(D[nt][2], 0.f);
                float v3 = fmaxf(D[nt][3], 0.f);
                int kt = nt >> 1, rp = (nt & 1) * 2;
                A[kt][rp]     = packh2(v0, v1);
                A[kt][rp + 1] = packh2(v2, v3);
            }
        } else {
            // fc17: dot with W17 + shfl reduce over the 4-lane column groups
            const float* w7 = sW17 + tig * 2;
            float s0 = 0.f, s1 = 0.f;
#pragma unroll
            for (int nt = 0; nt < 16; nt++) {
                float2 w2 = *reinterpret_cast<const float2*>(w7 + nt * 8);
                float v0 = fmaxf(D[nt][0], 0.f);
                float v1 = fmaxf(D[nt][1], 0.f);
                float v2 = fmaxf(D[nt][2], 0.f);
                float v3 = fmaxf(D[nt][3], 0.f);
                s0 = fmaf(v0, w2.x, fmaf(v1, w2.y, s0));
                s1 = fmaf(v2, w2.x, fmaf(v3, w2.y, s1));
            }
            s0 += __shfl_xor_sync(0xFFFFFFFFu, s0, 1);
            s0 += __shfl_xor_sync(0xFFFFFFFFu, s0, 2);
            s1 += __shfl_xor_sync(0xFFFFFFFFu, s1, 1);
            s1 += __shfl_xor_sync(0xFFFFFFFFu, s1, 2);
            if (tig == 0) {
                out[p0]     = s0 + b17v;
                out[p0 + 8] = s1 + b17v;
            }
        }
    }
}

// ---------------- launch ----------------
extern "C" void kernel_launch(void* const* d_in, const int* in_sizes, int n_in,
                              void* d_out, int out_size) {
    const float* x   = (const float*)d_in[0];
    const float* W1  = (const float*)d_in[1];
    const float* b1  = (const float*)d_in[2];
    const float* Ws  = (const float*)d_in[3];
    const float* bs  = (const float*)d_in[4];
    const float* W17 = (const float*)d_in[5];
    const float* b17 = (const float*)d_in[6];
    float* out = (float*)d_out;

    cudaFuncSetAttribute(mlp_kernel, cudaFuncAttributeMaxDynamicSharedMemorySize, SMEM_TOTAL);

    int npts = in_sizes[0] / 2;
    int nblk = npts / 128;

    prep_weights<<<(NLAYER * 64 * 32 + 255) / 256, 256>>>(Ws);
    mlp_kernel<<<nblk, 256, SMEM_TOTAL>>>(x, W1, b1, bs, W17, b17, out);
}

// round 9
// speedup vs baseline: 10.6413x; 1.1912x over previous
#include <cuda_runtime.h>
#include <cuda_fp16.h>
#include <stdint.h>

#define NLAYER 15
#define NSLOT  6               // ring of per-layer 32KB weight slots

// fp16 fragment-ordered weights: per layer 32KB.
// entry e = kt*8 + nt2: uint4 per lane = (b0 nt 2nt2, b1 nt 2nt2, b0 nt 2nt2+1, b1 nt 2nt2+1)
__device__ __align__(128) unsigned char g_wimg[NLAYER * 32768];

// ---------------- smem layout ----------------
#define SO_FULL   0                    // 6 mbarriers x 8B
#define SO_CNT    64                   // 15 uint32 counters
#define SO_W1     256                  // 256 floats
#define SO_B1     1280                 // 128 floats
#define SO_W17    1792                 // 128 floats
#define SO_BIAS   2304                 // 15*128 floats
#define SO_WBUF   10240                // 1024-aligned; 6 x 32768 ring
#define SMEM_TOTAL (10240 + NSLOT*32768)   // 206848 B

// ---------------- helpers ----------------
__device__ __forceinline__ uint32_t smem_u32(const void* p) {
    uint32_t a;
    asm("{ .reg .u64 t; cvta.to.shared.u64 t, %1; cvt.u32.u64 %0, t; }" : "=r"(a) : "l"(p));
    return a;
}
__device__ __forceinline__ void mbar_init(uint32_t mbar, uint32_t cnt) {
    asm volatile("mbarrier.init.shared.b64 [%0], %1;" :: "r"(mbar), "r"(cnt) : "memory");
}
__device__ __forceinline__ void mbar_expect_tx(uint32_t mbar, uint32_t bytes) {
    asm volatile("mbarrier.arrive.expect_tx.shared.b64 _, [%0], %1;" :: "r"(mbar), "r"(bytes) : "memory");
}
__device__ __forceinline__ void mbar_wait(uint32_t mbar, uint32_t parity) {
    asm volatile(
        "{\n\t.reg .pred P;\n\t"
        "WL_%=:\n\t"
        "mbarrier.try_wait.parity.acquire.cta.shared::cta.b64 P, [%0], %1, 0x989680;\n\t"
        "@P bra WD_%=;\n\t"
        "bra.uni WL_%=;\n\t"
        "WD_%=:\n\t}"
        :: "r"(mbar), "r"(parity) : "memory");
}
__device__ __forceinline__ void bulk_g2s(uint32_t dst, const void* src, uint32_t bytes, uint32_t mbar) {
    asm volatile("cp.async.bulk.shared::cta.global.mbarrier::complete_tx::bytes [%0], [%1], %2, [%3];"
                 :: "r"(dst), "l"(src), "r"(bytes), "r"(mbar) : "memory");
}
__device__ __forceinline__ uint32_t atom_inc_acqrel(uint32_t addr) {
    uint32_t old;
    asm volatile("atom.acq_rel.cta.shared::cta.add.u32 %0, [%1], 1;"
                 : "=r"(old) : "r"(addr) : "memory");
    return old;
}
__device__ __forceinline__ uint4 lds128(uint32_t addr) {
    uint4 v;
    asm volatile("ld.shared.v4.b32 {%0,%1,%2,%3}, [%4];"
                 : "=r"(v.x), "=r"(v.y), "=r"(v.z), "=r"(v.w) : "r"(addr));
    return v;
}
__device__ __forceinline__ void mma16816(float* d, const uint32_t* a, uint32_t b0, uint32_t b1) {
    asm volatile(
        "mma.sync.aligned.m16n8k16.row.col.f32.f16.f16.f32 "
        "{%0,%1,%2,%3}, {%4,%5,%6,%7}, {%8,%9}, {%0,%1,%2,%3};"
        : "+f"(d[0]), "+f"(d[1]), "+f"(d[2]), "+f"(d[3])
        : "r"(a[0]), "r"(a[1]), "r"(a[2]), "r"(a[3]), "r"(b0), "r"(b1));
}
__device__ __forceinline__ uint32_t packh2(float a, float b) {
    __half2 h = __float22half2_rn(make_float2(a, b));
    return *reinterpret_cast<uint32_t*>(&h);
}

// ---------------- prep: weights -> fp16 per-lane fragment layout ----------------
__global__ void prep_weights(const float* __restrict__ Ws) {
    int idx = blockIdx.x * blockDim.x + threadIdx.x;
    if (idx >= NLAYER * 64 * 32) return;
    int lane  = idx & 31;
    int e     = (idx >> 5) & 63;   // kt*8 + nt2
    int layer = idx >> 11;
    int kt  = e >> 3;
    int nt2 = e & 7;
    int tig = lane & 3;
    int g   = lane >> 2;
    int k0 = kt * 16 + tig * 2;
    const float* W = Ws + layer * 16384;

    auto pk = [&](int k, int n) -> uint32_t {
        return packh2(W[k * 128 + n], W[(k + 1) * 128 + n]);
    };
    int n0 = nt2 * 16 + g;
    uint4 r;
    r.x = pk(k0,     n0);
    r.y = pk(k0 + 8, n0);
    r.z = pk(k0,     n0 + 8);
    r.w = pk(k0 + 8, n0 + 8);
    *reinterpret_cast<uint4*>(&g_wimg[(size_t)layer * 32768u + (size_t)e * 512u
                                      + (size_t)lane * 16u]) = r;
}

// One mid layer for a 32-row warp tile: A0/A1 (two m16 tiles) -> B0/B1.
// nt2-outer keeps only 16 D floats live; each weight load feeds 4 MMAs.
__device__ __forceinline__ void mlp_step(
    uint32_t wb, const float* bi,
    uint32_t (&A0)[8][4], uint32_t (&A1)[8][4],
    uint32_t (&B0)[8][4], uint32_t (&B1)[8][4])
{
#pragma unroll
    for (int nt2 = 0; nt2 < 8; nt2++) {
        float2 bb0 = *reinterpret_cast<const float2*>(bi + (2 * nt2) * 8);
        float2 bb1 = *reinterpret_cast<const float2*>(bi + (2 * nt2 + 1) * 8);
        float D[4][4];
        D[0][0] = bb0.x; D[0][1] = bb0.y; D[0][2] = bb0.x; D[0][3] = bb0.y;
        D[1][0] = bb1.x; D[1][1] = bb1.y; D[1][2] = bb1.x; D[1][3] = bb1.y;
        D[2][0] = bb0.x; D[2][1] = bb0.y; D[2][2] = bb0.x; D[2][3] = bb0.y;
        D[3][0] = bb1.x; D[3][1] = bb1.y; D[3][2] = bb1.x; D[3][3] = bb1.y;
#pragma unroll
        for (int kt = 0; kt < 8; kt++) {
            uint4 w = lds128(wb + (uint32_t)((kt * 8 + nt2) * 512));
            mma16816(D[0], A0[kt], w.x, w.y);
            mma16816(D[1], A0[kt], w.z, w.w);
            mma16816(D[2], A1[kt], w.x, w.y);
            mma16816(D[3], A1[kt], w.z, w.w);
        }
        B0[nt2][0] = packh2(fmaxf(D[0][0], 0.f), fmaxf(D[0][1], 0.f));
        B0[nt2][1] = packh2(fmaxf(D[0][2], 0.f), fmaxf(D[0][3], 0.f));
        B0[nt2][2] = packh2(fmaxf(D[1][0], 0.f), fmaxf(D[1][1], 0.f));
        B0[nt2][3] = packh2(fmaxf(D[1][2], 0.f), fmaxf(D[1][3], 0.f));
        B1[nt2][0] = packh2(fmaxf(D[2][0], 0.f), fmaxf(D[2][1], 0.f));
        B1[nt2][1] = packh2(fmaxf(D[2][2], 0.f), fmaxf(D[2][3], 0.f));
        B1[nt2][2] = packh2(fmaxf(D[3][0], 0.f), fmaxf(D[3][1], 0.f));
        B1[nt2][3] = packh2(fmaxf(D[3][2], 0.f), fmaxf(D[3][3], 0.f));
    }
}

// Final hidden layer fused with fc17: returns 4 partial dots (rows g,g+8,g+16,g+24).
__device__ __forceinline__ float4 mlp_last(
    uint32_t wb, const float* bi, const float* w7,
    uint32_t (&A0)[8][4], uint32_t (&A1)[8][4])
{
    float s0 = 0.f, s1 = 0.f, s2 = 0.f, s3 = 0.f;
#pragma unroll
    for (int nt2 = 0; nt2 < 8; nt2++) {
        float2 bb0 = *reinterpret_cast<const float2*>(bi + (2 * nt2) * 8);
        float2 bb1 = *reinterpret_cast<const float2*>(bi + (2 * nt2 + 1) * 8);
        float D[4][4];
        D[0][0] = bb0.x; D[0][1] = bb0.y; D[0][2] = bb0.x; D[0][3] = bb0.y;
        D[1][0] = bb1.x; D[1][1] = bb1.y; D[1][2] = bb1.x; D[1][3] = bb1.y;
        D[2][0] = bb0.x; D[2][1] = bb0.y; D[2][2] = bb0.x; D[2][3] = bb0.y;
        D[3][0] = bb1.x; D[3][1] = bb1.y; D[3][2] = bb1.x; D[3][3] = bb1.y;
#pragma unroll
        for (int kt = 0; kt < 8; kt++) {
            uint4 w = lds128(wb + (uint32_t)((kt * 8 + nt2) * 512));
            mma16816(D[0], A0[kt], w.x, w.y);
            mma16816(D[1], A0[kt], w.z, w.w);
            mma16816(D[2], A1[kt], w.x, w.y);
            mma16816(D[3], A1[kt], w.z, w.w);
        }
        float2 wa = *reinterpret_cast<const float2*>(w7 + (2 * nt2) * 8);
        float2 wc = *reinterpret_cast<const float2*>(w7 + (2 * nt2 + 1) * 8);
        s0 = fmaf(fmaxf(D[0][0], 0.f), wa.x, fmaf(fmaxf(D[0][1], 0.f), wa.y, s0));
        s1 = fmaf(fmaxf(D[0][2], 0.f), wa.x, fmaf(fmaxf(D[0][3], 0.f), wa.y, s1));
        s0 = fmaf(fmaxf(D[1][0], 0.f), wc.x, fmaf(fmaxf(D[1][1], 0.f), wc.y, s0));
        s1 = fmaf(fmaxf(D[1][2], 0.f), wc.x, fmaf(fmaxf(D[1][3], 0.f), wc.y, s1));
        s2 = fmaf(fmaxf(D[2][0], 0.f), wa.x, fmaf(fmaxf(D[2][1], 0.f), wa.y, s2));
        s3 = fmaf(fmaxf(D[2][2], 0.f), wa.x, fmaf(fmaxf(D[2][3], 0.f), wa.y, s3));
        s2 = fmaf(fmaxf(D[3][0], 0.f), wc.x, fmaf(fmaxf(D[3][1], 0.f), wc.y, s2));
        s3 = fmaf(fmaxf(D[3][2], 0.f), wc.x, fmaf(fmaxf(D[3][3], 0.f), wc.y, s3));
    }
    return make_float4(s0, s1, s2, s3);
}

// ---------------- main fused MLP kernel ------------------------------------
__global__ void __launch_bounds__(256, 1)
mlp_kernel(const float* __restrict__ x, const float* __restrict__ W1,
           const float* __restrict__ b1, const float* __restrict__ bs,
           const float* __restrict__ W17, const float* __restrict__ b17,
           float* __restrict__ out) {
    extern __shared__ __align__(1024) unsigned char smem[];
    uint32_t sb = smem_u32(smem);
    int tid  = threadIdx.x;
    int wid  = tid >> 5;
    int lane = tid & 31;
    int g    = lane >> 2;
    int tig  = lane & 3;

    float* sW1  = reinterpret_cast<float*>(smem + SO_W1);
    float* sB1  = reinterpret_cast<float*>(smem + SO_B1);
    float* sW17 = reinterpret_cast<float*>(smem + SO_W17);
    float* sBias= reinterpret_cast<float*>(smem + SO_BIAS);

    if (tid < NSLOT) mbar_init(sb + SO_FULL + 8u * tid, 1);
    if (tid < 256) sW1[tid] = W1[tid];
    if (tid < 128) { sB1[tid] = b1[tid]; sW17[tid] = W17[tid]; }
    if (tid < NLAYER) reinterpret_cast<uint32_t*>(smem + SO_CNT)[tid] = 0;
    for (int idx = tid; idx < NLAYER * 128; idx += 256) sBias[idx] = bs[idx];
    __syncthreads();

    if (tid == 0) {
#pragma unroll
        for (int j = 0; j < NSLOT; j++) {
            mbar_expect_tx(sb + SO_FULL + 8u * j, 32768);
            bulk_g2s(sb + SO_WBUF + 32768u * j, &g_wimg[(size_t)j * 32768u], 32768,
                     sb + SO_FULL + 8u * j);
        }
    }

    float b17v = b17[0];

    // ---- fc1: 32 rows per warp -> two m16 fragment sets ----
    size_t p0 = (size_t)blockIdx.x * 256 + (size_t)(wid * 32 + g);
    float2 xa = reinterpret_cast<const float2*>(x)[p0];        // row g
    float2 xb = reinterpret_cast<const float2*>(x)[p0 + 8];    // row g+8
    float2 xc = reinterpret_cast<const float2*>(x)[p0 + 16];   // row g+16
    float2 xd = reinterpret_cast<const float2*>(x)[p0 + 24];   // row g+24

    uint32_t A0[8][4], A1[8][4], B0[8][4], B1[8][4];
#pragma unroll
    for (int kt = 0; kt < 8; kt++) {
        int c = kt * 16 + tig * 2;
#pragma unroll
        for (int q = 0; q < 2; q++) {
            int cc = c + q * 8;
            float w0 = sW1[cc],     w0y = sW1[128 + cc],     bb0 = sB1[cc];
            float w1 = sW1[cc + 1], w1y = sW1[128 + cc + 1], bb1 = sB1[cc + 1];
            float va0 = fmaxf(fmaf(xa.x, w0, fmaf(xa.y, w0y, bb0)), 0.f);
            float va1 = fmaxf(fmaf(xa.x, w1, fmaf(xa.y, w1y, bb1)), 0.f);
            float vb0 = fmaxf(fmaf(xb.x, w0, fmaf(xb.y, w0y, bb0)), 0.f);
            float vb1 = fmaxf(fmaf(xb.x, w1, fmaf(xb.y, w1y, bb1)), 0.f);
            float vc0 = fmaxf(fmaf(xc.x, w0, fmaf(xc.y, w0y, bb0)), 0.f);
            float vc1 = fmaxf(fmaf(xc.x, w1, fmaf(xc.y, w1y, bb1)), 0.f);
            float vd0 = fmaxf(fmaf(xd.x, w0, fmaf(xd.y, w0y, bb0)), 0.f);
            float vd1 = fmaxf(fmaf(xd.x, w1, fmaf(xd.y, w1y, bb1)), 0.f);
            A0[kt][2 * q]     = packh2(va0, va1);
            A0[kt][2 * q + 1] = packh2(vb0, vb1);
            A1[kt][2 * q]     = packh2(vc0, vc1);
            A1[kt][2 * q + 1] = packh2(vd0, vd1);
        }
    }

    // seed warp-phase stagger
    if (wid) __nanosleep((unsigned)(wid * 250));

    const float* biasBase = sBias + tig * 2;

    auto ring_advance = [&](int i, int slot) {
        if (lane == 0) {
            uint32_t old = atom_inc_acqrel(sb + SO_CNT + 4u * (uint32_t)i);
            if (old == 7 && i + NSLOT < NLAYER) {
                asm volatile("fence.proxy.async.shared::cta;" ::: "memory");
                uint32_t fb = sb + SO_FULL + 8u * (uint32_t)slot;
                mbar_expect_tx(fb, 32768);
                bulk_g2s(sb + SO_WBUF + (uint32_t)slot * 32768u,
                         &g_wimg[(size_t)(i + NSLOT) * 32768u], 32768, fb);
            }
        }
    };

    // 7 layer pairs with register ping-pong A<->B, then final fused layer.
    for (int ii = 0; ii < 7; ii++) {
        int i0 = 2 * ii, i1 = 2 * ii + 1;
        {
            int slot = i0 % NSLOT;
            mbar_wait(sb + SO_FULL + 8u * slot, (uint32_t)((i0 / NSLOT) & 1));
            uint32_t wb = sb + SO_WBUF + (uint32_t)slot * 32768u + (uint32_t)lane * 16u;
            mlp_step(wb, biasBase + i0 * 128, A0, A1, B0, B1);
            ring_advance(i0, slot);
        }
        {
            int slot = i1 % NSLOT;
            mbar_wait(sb + SO_FULL + 8u * slot, (uint32_t)((i1 / NSLOT) & 1));
            uint32_t wb = sb + SO_WBUF + (uint32_t)slot * 32768u + (uint32_t)lane * 16u;
            mlp_step(wb, biasBase + i1 * 128, B0, B1, A0, A1);
            ring_advance(i1, slot);
        }
    }

    {   // layer 14 + fc17
        const int i = NLAYER - 1;
        int slot = i % NSLOT;
        mbar_wait(sb + SO_FULL + 8u * slot, (uint32_t)((i / NSLOT) & 1));
        uint32_t wb = sb + SO_WBUF + (uint32_t)slot * 32768u + (uint32_t)lane * 16u;
        float4 s = mlp_last(wb, biasBase + i * 128, sW17 + tig * 2, A0, A1);
        float s0 = s.x, s1 = s.y, s2 = s.z, s3 = s.w;
        s0 += __shfl_xor_sync(0xFFFFFFFFu, s0, 1);
        s0 += __shfl_xor_sync(0xFFFFFFFFu, s0, 2);
        s1 += __shfl_xor_sync(0xFFFFFFFFu, s1, 1);
        s1 += __shfl_xor_sync(0xFFFFFFFFu, s1, 2);
        s2 += __shfl_xor_sync(0xFFFFFFFFu, s2, 1);
        s2 += __shfl_xor_sync(0xFFFFFFFFu, s2, 2);
        s3 += __shfl_xor_sync(0xFFFFFFFFu, s3, 1);
        s3 += __shfl_xor_sync(0xFFFFFFFFu, s3, 2);
        if (tig == 0) {
            out[p0]      = s0 + b17v;
            out[p0 + 8]  = s1 + b17v;
            out[p0 + 16] = s2 + b17v;
            out[p0 + 24] = s3 + b17v;
        }
    }
}

// ---------------- launch ----------------
extern "C" void kernel_launch(void* const* d_in, const int* in_sizes, int n_in,
                              void* d_out, int out_size) {
    const float* x   = (const float*)d_in[0];
    const float* W1  = (const float*)d_in[1];
    const float* b1  = (const float*)d_in[2];
    const float* Ws  = (const float*)d_in[3];
    const float* bs  = (const float*)d_in[4];
    const float* W17 = (const float*)d_in[5];
    const float* b17 = (const float*)d_in[6];
    float* out = (float*)d_out;

    cudaFuncSetAttribute(mlp_kernel, cudaFuncAttributeMaxDynamicSharedMemorySize, SMEM_TOTAL);

    int npts = in_sizes[0] / 2;
    int nblk = npts / 256;

    prep_weights<<<(NLAYER * 64 * 32 + 255) / 256, 256>>>(Ws);
    mlp_kernel<<<nblk, 256, SMEM_TOTAL>>>(x, W1, b1, bs, W17, b17, out);
}

// round 11
// speedup vs baseline: 10.7237x; 1.0077x over previous
#include <cuda_runtime.h>
#include <cuda_fp16.h>
#include <stdint.h>

#define NLAYER 15
#define NSLOT  6               // ring of per-layer 32KB weight slots

// fp16 fragment-ordered weights: per layer 32KB.
// entry e = kt*8 + nt2: uint4 per lane = (b0 nt 2nt2, b1 nt 2nt2, b0 nt 2nt2+1, b1 nt 2nt2+1)
__device__ __align__(128) unsigned char g_wimg[NLAYER * 32768];

// ---------------- smem layout ----------------
#define SO_FULL   0                    // 6 mbarriers x 8B
#define SO_CNT    64                   // 15 uint32 counters
#define SO_W1     256                  // 256 floats
#define SO_B1     1280                 // 128 floats
#define SO_W17    1792                 // 128 floats
#define SO_BIAS   2304                 // 15*128 floats
#define SO_WBUF   10240                // 1024-aligned; 6 x 32768 ring
#define SMEM_TOTAL (10240 + NSLOT*32768)   // 206848 B

// ---------------- helpers ----------------
__device__ __forceinline__ uint32_t smem_u32(const void* p) {
    uint32_t a;
    asm("{ .reg .u64 t; cvta.to.shared.u64 t, %1; cvt.u32.u64 %0, t; }" : "=r"(a) : "l"(p));
    return a;
}
__device__ __forceinline__ void mbar_init(uint32_t mbar, uint32_t cnt) {
    asm volatile("mbarrier.init.shared.b64 [%0], %1;" :: "r"(mbar), "r"(cnt) : "memory");
}
__device__ __forceinline__ void mbar_expect_tx(uint32_t mbar, uint32_t bytes) {
    asm volatile("mbarrier.arrive.expect_tx.shared.b64 _, [%0], %1;" :: "r"(mbar), "r"(bytes) : "memory");
}
__device__ __forceinline__ void mbar_wait(uint32_t mbar, uint32_t parity) {
    asm volatile(
        "{\n\t.reg .pred P;\n\t"
        "WL_%=:\n\t"
        "mbarrier.try_wait.parity.acquire.cta.shared::cta.b64 P, [%0], %1, 0x989680;\n\t"
        "@P bra WD_%=;\n\t"
        "bra.uni WL_%=;\n\t"
        "WD_%=:\n\t}"
        :: "r"(mbar), "r"(parity) : "memory");
}
__device__ __forceinline__ void bulk_g2s(uint32_t dst, const void* src, uint32_t bytes, uint32_t mbar) {
    asm volatile("cp.async.bulk.shared::cta.global.mbarrier::complete_tx::bytes [%0], [%1], %2, [%3];"
                 :: "r"(dst), "l"(src), "r"(bytes), "r"(mbar) : "memory");
}
__device__ __forceinline__ uint32_t atom_inc_acqrel(uint32_t addr) {
    uint32_t old;
    asm volatile("atom.acq_rel.cta.shared::cta.add.u32 %0, [%1], 1;"
                 : "=r"(old) : "r"(addr) : "memory");
    return old;
}
__device__ __forceinline__ uint4 lds128(uint32_t addr) {
    uint4 v;
    asm volatile("ld.shared.v4.b32 {%0,%1,%2,%3}, [%4];"
                 : "=r"(v.x), "=r"(v.y), "=r"(v.z), "=r"(v.w) : "r"(addr));
    return v;
}
__device__ __forceinline__ void mma16816(float* d, const uint32_t* a, uint32_t b0, uint32_t b1) {
    asm volatile(
        "mma.sync.aligned.m16n8k16.row.col.f32.f16.f16.f32 "
        "{%0,%1,%2,%3}, {%4,%5,%6,%7}, {%8,%9}, {%0,%1,%2,%3};"
        : "+f"(d[0]), "+f"(d[1]), "+f"(d[2]), "+f"(d[3])
        : "r"(a[0]), "r"(a[1]), "r"(a[2]), "r"(a[3]), "r"(b0), "r"(b1));
}
__device__ __forceinline__ uint32_t packh2(float a, float b) {
    __half2 h = __float22half2_rn(make_float2(a, b));
    return *reinterpret_cast<uint32_t*>(&h);
}
// pack two f32 to f16x2, then relu in half2 (1 pack + 1 HMAX2 vs 2 FMNMX + 1 pack)
__device__ __forceinline__ uint32_t packrelu2(float a, float b) {
    __half2 h = __float22half2_rn(make_float2(a, b));
    h = __hmax2(h, __float2half2_rn(0.f));
    return *reinterpret_cast<uint32_t*>(&h);
}

// ---------------- prep: weights -> fp16 per-lane fragment layout ----------------
__global__ void prep_weights(const float* __restrict__ Ws) {
    int idx = blockIdx.x * blockDim.x + threadIdx.x;
    if (idx >= NLAYER * 64 * 32) return;
    int lane  = idx & 31;
    int e     = (idx >> 5) & 63;   // kt*8 + nt2
    int layer = idx >> 11;
    int kt  = e >> 3;
    int nt2 = e & 7;
    int tig = lane & 3;
    int g   = lane >> 2;
    int k0 = kt * 16 + tig * 2;
    const float* W = Ws + layer * 16384;

    auto pk = [&](int k, int n) -> uint32_t {
        return packh2(W[k * 128 + n], W[(k + 1) * 128 + n]);
    };
    int n0 = nt2 * 16 + g;
    uint4 r;
    r.x = pk(k0,     n0);
    r.y = pk(k0 + 8, n0);
    r.z = pk(k0,     n0 + 8);
    r.w = pk(k0 + 8, n0 + 8);
    *reinterpret_cast<uint4*>(&g_wimg[(size_t)layer * 32768u + (size_t)e * 512u
                                      + (size_t)lane * 16u]) = r;
}

// One mid layer for a 32-row warp tile: A0/A1 -> B0/B1.
// Explicit reg double-buffer of weight loads: kt+1's LDS issued before kt's MMAs.
__device__ __forceinline__ void mlp_step(
    uint32_t wb, const float* bi,
    uint32_t (&A0)[8][4], uint32_t (&A1)[8][4],
    uint32_t (&B0)[8][4], uint32_t (&B1)[8][4])
{
#pragma unroll
    for (int nt2 = 0; nt2 < 8; nt2++) {
        float2 bb0 = *reinterpret_cast<const float2*>(bi + (2 * nt2) * 8);
        float2 bb1 = *reinterpret_cast<const float2*>(bi + (2 * nt2 + 1) * 8);
        float D[4][4];
        D[0][0] = bb0.x; D[0][1] = bb0.y; D[0][2] = bb0.x; D[0][3] = bb0.y;
        D[1][0] = bb1.x; D[1][1] = bb1.y; D[1][2] = bb1.x; D[1][3] = bb1.y;
        D[2][0] = bb0.x; D[2][1] = bb0.y; D[2][2] = bb0.x; D[2][3] = bb0.y;
        D[3][0] = bb1.x; D[3][1] = bb1.y; D[3][2] = bb1.x; D[3][3] = bb1.y;

        uint4 w = lds128(wb + (uint32_t)(nt2 * 512));     // kt = 0
#pragma unroll
        for (int kt = 0; kt < 8; kt++) {
            uint4 wn;
            if (kt < 7) wn = lds128(wb + (uint32_t)(((kt + 1) * 8 + nt2) * 512));
            mma16816(D[0], A0[kt], w.x, w.y);
            mma16816(D[1], A0[kt], w.z, w.w);
            mma16816(D[2], A1[kt], w.x, w.y);
            mma16816(D[3], A1[kt], w.z, w.w);
            if (kt < 7) w = wn;
        }
        B0[nt2][0] = packrelu2(D[0][0], D[0][1]);
        B0[nt2][1] = packrelu2(D[0][2], D[0][3]);
        B0[nt2][2] = packrelu2(D[1][0], D[1][1]);
        B0[nt2][3] = packrelu2(D[1][2], D[1][3]);
        B1[nt2][0] = packrelu2(D[2][0], D[2][1]);
        B1[nt2][1] = packrelu2(D[2][2], D[2][3]);
        B1[nt2][2] = packrelu2(D[3][0], D[3][1]);
        B1[nt2][3] = packrelu2(D[3][2], D[3][3]);
    }
}

// Final hidden layer fused with fc17: returns 4 partial dots (rows g,g+8,g+16,g+24).
__device__ __forceinline__ float4 mlp_last(
    uint32_t wb, const float* bi, const float* w7,
    uint32_t (&A0)[8][4], uint32_t (&A1)[8][4])
{
    float s0 = 0.f, s1 = 0.f, s2 = 0.f, s3 = 0.f;
#pragma unroll
    for (int nt2 = 0; nt2 < 8; nt2++) {
        float2 bb0 = *reinterpret_cast<const float2*>(bi + (2 * nt2) * 8);
        float2 bb1 = *reinterpret_cast<const float2*>(bi + (2 * nt2 + 1) * 8);
        float D[4][4];
        D[0][0] = bb0.x; D[0][1] = bb0.y; D[0][2] = bb0.x; D[0][3] = bb0.y;
        D[1][0] = bb1.x; D[1][1] = bb1.y; D[1][2] = bb1.x; D[1][3] = bb1.y;
        D[2][0] = bb0.x; D[2][1] = bb0.y; D[2][2] = bb0.x; D[2][3] = bb0.y;
        D[3][0] = bb1.x; D[3][1] = bb1.y; D[3][2] = bb1.x; D[3][3] = bb1.y;

        uint4 w = lds128(wb + (uint32_t)(nt2 * 512));
#pragma unroll
        for (int kt = 0; kt < 8; kt++) {
            uint4 wn;
            if (kt < 7) wn = lds128(wb + (uint32_t)(((kt + 1) * 8 + nt2) * 512));
            mma16816(D[0], A0[kt], w.x, w.y);
            mma16816(D[1], A0[kt], w.z, w.w);
            mma16816(D[2], A1[kt], w.x, w.y);
            mma16816(D[3], A1[kt], w.z, w.w);
            if (kt < 7) w = wn;
        }
        float2 wa = *reinterpret_cast<const float2*>(w7 + (2 * nt2) * 8);
        float2 wc = *reinterpret_cast<const float2*>(w7 + (2 * nt2 + 1) * 8);
        s0 = fmaf(fmaxf(D[0][0], 0.f), wa.x, fmaf(fmaxf(D[0][1], 0.f), wa.y, s0));
        s1 = fmaf(fmaxf(D[0][2], 0.f), wa.x, fmaf(fmaxf(D[0][3], 0.f), wa.y, s1));
        s0 = fmaf(fmaxf(D[1][0], 0.f), wc.x, fmaf(fmaxf(D[1][1], 0.f), wc.y, s0));
        s1 = fmaf(fmaxf(D[1][2], 0.f), wc.x, fmaf(fmaxf(D[1][3], 0.f), wc.y, s1));
        s2 = fmaf(fmaxf(D[2][0], 0.f), wa.x, fmaf(fmaxf(D[2][1], 0.f), wa.y, s2));
        s3 = fmaf(fmaxf(D[2][2], 0.f), wa.x, fmaf(fmaxf(D[2][3], 0.f), wa.y, s3));
        s2 = fmaf(fmaxf(D[3][0], 0.f), wc.x, fmaf(fmaxf(D[3][1], 0.f), wc.y, s2));
        s3 = fmaf(fmaxf(D[3][2], 0.f), wc.x, fmaf(fmaxf(D[3][3], 0.f), wc.y, s3));
    }
    return make_float4(s0, s1, s2, s3);
}

// ---------------- main fused MLP kernel ------------------------------------
__global__ void __launch_bounds__(256, 1)
mlp_kernel(const float* __restrict__ x, const float* __restrict__ W1,
           const float* __restrict__ b1, const float* __restrict__ bs,
           const float* __restrict__ W17, const float* __restrict__ b17,
           float* __restrict__ out) {
    extern __shared__ __align__(1024) unsigned char smem[];
    uint32_t sb = smem_u32(smem);
    int tid  = threadIdx.x;
    int wid  = tid >> 5;
    int lane = tid & 31;
    int g    = lane >> 2;
    int tig  = lane & 3;

    float* sW1  = reinterpret_cast<float*>(smem + SO_W1);
    float* sB1  = reinterpret_cast<float*>(smem + SO_B1);
    float* sW17 = reinterpret_cast<float*>(smem + SO_W17);
    float* sBias= reinterpret_cast<float*>(smem + SO_BIAS);

    if (tid < NSLOT) mbar_init(sb + SO_FULL + 8u * tid, 1);
    if (tid < 256) sW1[tid] = W1[tid];
    if (tid < 128) { sB1[tid] = b1[tid]; sW17[tid] = W17[tid]; }
    if (tid < NLAYER) reinterpret_cast<uint32_t*>(smem + SO_CNT)[tid] = 0;
    for (int idx = tid; idx < NLAYER * 128; idx += 256) sBias[idx] = bs[idx];
    __syncthreads();

    if (tid == 0) {
#pragma unroll
        for (int j = 0; j < NSLOT; j++) {
            mbar_expect_tx(sb + SO_FULL + 8u * j, 32768);
            bulk_g2s(sb + SO_WBUF + 32768u * j, &g_wimg[(size_t)j * 32768u], 32768,
                     sb + SO_FULL + 8u * j);
        }
    }

    float b17v = b17[0];

    // ---- fc1: 32 rows per warp -> two m16 fragment sets ----
    size_t p0 = (size_t)blockIdx.x * 256 + (size_t)(wid * 32 + g);
    float2 xa = reinterpret_cast<const float2*>(x)[p0];
    float2 xb = reinterpret_cast<const float2*>(x)[p0 + 8];
    float2 xc = reinterpret_cast<const float2*>(x)[p0 + 16];
    float2 xd = reinterpret_cast<const float2*>(x)[p0 + 24];

    uint32_t A0[8][4], A1[8][4], B0[8][4], B1[8][4];
#pragma unroll
    for (int kt = 0; kt < 8; kt++) {
        int c = kt * 16 + tig * 2;
#pragma unroll
        for (int q = 0; q < 2; q++) {
            int cc = c + q * 8;
            float w0 = sW1[cc],     w0y = sW1[128 + cc],     bb0 = sB1[cc];
            float w1 = sW1[cc + 1], w1y = sW1[128 + cc + 1], bb1 = sB1[cc + 1];
            float va0 = fmaf(xa.x, w0, fmaf(xa.y, w0y, bb0));
            float va1 = fmaf(xa.x, w1, fmaf(xa.y, w1y, bb1));
            float vb0 = fmaf(xb.x, w0, fmaf(xb.y, w0y, bb0));
            float vb1 = fmaf(xb.x, w1, fmaf(xb.y, w1y, bb1));
            float vc0 = fmaf(xc.x, w0, fmaf(xc.y, w0y, bb0));
            float vc1 = fmaf(xc.x, w1, fmaf(xc.y, w1y, bb1));
            float vd0 = fmaf(xd.x, w0, fmaf(xd.y, w0y, bb0));
            float vd1 = fmaf(xd.x, w1, fmaf(xd.y, w1y, bb1));
            A0[kt][2 * q]     = packrelu2(va0, va1);
            A0[kt][2 * q + 1] = packrelu2(vb0, vb1);
            A1[kt][2 * q]     = packrelu2(vc0, vc1);
            A1[kt][2 * q + 1] = packrelu2(vd0, vd1);
        }
    }

    // seed warp-phase stagger
    if (wid) __nanosleep((unsigned)(wid * 250));

    const float* biasBase = sBias + tig * 2;

    auto ring_advance = [&](int i, int slot) {
        if (lane == 0) {
            uint32_t old = atom_inc_acqrel(sb + SO_CNT + 4u * (uint32_t)i);
            if (old == 7 && i + NSLOT < NLAYER) {
                asm volatile("fence.proxy.async.shared::cta;" ::: "memory");
                uint32_t fb = sb + SO_FULL + 8u * (uint32_t)slot;
                mbar_expect_tx(fb, 32768);
                bulk_g2s(sb + SO_WBUF + (uint32_t)slot * 32768u,
                         &g_wimg[(size_t)(i + NSLOT) * 32768u], 32768, fb);
            }
        }
    };

    // 7 layer pairs with register ping-pong A<->B, then final fused layer.
    for (int ii = 0; ii < 7; ii++) {
        int i0 = 2 * ii, i1 = 2 * ii + 1;
        {
            int slot = i0 % NSLOT;
            mbar_wait(sb + SO_FULL + 8u * slot, (uint32_t)((i0 / NSLOT) & 1));
            uint32_t wb = sb + SO_WBUF + (uint32_t)slot * 32768u + (uint32_t)lane * 16u;
            mlp_step(wb, biasBase + i0 * 128, A0, A1, B0, B1);
            ring_advance(i0, slot);
        }
        {
            int slot = i1 % NSLOT;
            mbar_wait(sb + SO_FULL + 8u * slot, (uint32_t)((i1 / NSLOT) & 1));
            uint32_t wb = sb + SO_WBUF + (uint32_t)slot * 32768u + (uint32_t)lane * 16u;
            mlp_step(wb, biasBase + i1 * 128, B0, B1, A0, A1);
            ring_advance(i1, slot);
        }
    }

    {   // layer 14 + fc17
        const int i = NLAYER - 1;
        int slot = i % NSLOT;
        mbar_wait(sb + SO_FULL + 8u * slot, (uint32_t)((i / NSLOT) & 1));
        uint32_t wb = sb + SO_WBUF + (uint32_t)slot * 32768u + (uint32_t)lane * 16u;
        float4 s = mlp_last(wb, biasBase + i * 128, sW17 + tig * 2, A0, A1);
        float s0 = s.x, s1 = s.y, s2 = s.z, s3 = s.w;
        s0 += __shfl_xor_sync(0xFFFFFFFFu, s0, 1);
        s0 += __shfl_xor_sync(0xFFFFFFFFu, s0, 2);
        s1 += __shfl_xor_sync(0xFFFFFFFFu, s1, 1);
        s1 += __shfl_xor_sync(0xFFFFFFFFu, s1, 2);
        s2 += __shfl_xor_sync(0xFFFFFFFFu, s2, 1);
        s2 += __shfl_xor_sync(0xFFFFFFFFu, s2, 2);
        s3 += __shfl_xor_sync(0xFFFFFFFFu, s3, 1);
        s3 += __shfl_xor_sync(0xFFFFFFFFu, s3, 2);
        if (tig == 0) {
            out[p0]      = s0 + b17v;
            out[p0 + 8]  = s1 + b17v;
            out[p0 + 16] = s2 + b17v;
            out[p0 + 24] = s3 + b17v;
        }
    }
}

// ---------------- launch ----------------
extern "C" void kernel_launch(void* const* d_in, const int* in_sizes, int n_in,
                              void* d_out, int out_size) {
    const float* x   = (const float*)d_in[0];
    const float* W1  = (const float*)d_in[1];
    const float* b1  = (const float*)d_in[2];
    const float* Ws  = (const float*)d_in[3];
    const float* bs  = (const float*)d_in[4];
    const float* W17 = (const float*)d_in[5];
    const float* b17 = (const float*)d_in[6];
    float* out = (float*)d_out;

    cudaFuncSetAttribute(mlp_kernel, cudaFuncAttributeMaxDynamicSharedMemorySize, SMEM_TOTAL);

    int npts = in_sizes[0] / 2;
    int nblk = npts / 256;

    prep_weights<<<(NLAYER * 64 * 32 + 255) / 256, 256>>>(Ws);
    mlp_kernel<<<nblk, 256, SMEM_TOTAL>>>(x, W1, b1, bs, W17, b17, out);
}

// round 12
// speedup vs baseline: 11.3143x; 1.0551x over previous
#include <cuda_runtime.h>
#include <cuda_fp16.h>
#include <stdint.h>

#define NLAYER 15
#define NSLOT  6               // ring of 32KB weight slots (layer chunks)

// fp16 fragment-ordered weights: per layer 32KB.
// entry e = kt*8 + nt2: uint4 per lane = (b0 nt 2nt2, b1 nt 2nt2, b0 nt 2nt2+1, b1 nt 2nt2+1)
__device__ __align__(128) unsigned char g_wimg[NLAYER * 32768];

// ---------------- smem layout ----------------
#define SO_FULL   0                    // 6 mbarriers x 8B
#define SO_CNT    64                   // 16 uint32 monotonic chunk counters
#define SO_W1     256                  // 256 floats
#define SO_B1     1280                 // 128 floats
#define SO_W17    1792                 // 128 floats
#define SO_BIAS   2304                 // 15*128 floats
#define SO_WBUF   10240                // 1024-aligned; 6 x 32768 ring
#define SMEM_TOTAL (10240 + NSLOT*32768)   // 206848 B

// ---------------- helpers ----------------
__device__ __forceinline__ uint32_t smem_u32(const void* p) {
    uint32_t a;
    asm("{ .reg .u64 t; cvta.to.shared.u64 t, %1; cvt.u32.u64 %0, t; }" : "=r"(a) : "l"(p));
    return a;
}
__device__ __forceinline__ void mbar_init(uint32_t mbar, uint32_t cnt) {
    asm volatile("mbarrier.init.shared.b64 [%0], %1;" :: "r"(mbar), "r"(cnt) : "memory");
}
__device__ __forceinline__ void mbar_expect_tx(uint32_t mbar, uint32_t bytes) {
    asm volatile("mbarrier.arrive.expect_tx.shared.b64 _, [%0], %1;" :: "r"(mbar), "r"(bytes) : "memory");
}
__device__ __forceinline__ void mbar_wait(uint32_t mbar, uint32_t parity) {
    asm volatile(
        "{\n\t.reg .pred P;\n\t"
        "WL_%=:\n\t"
        "mbarrier.try_wait.parity.acquire.cta.shared::cta.b64 P, [%0], %1, 0x989680;\n\t"
        "@P bra WD_%=;\n\t"
        "bra.uni WL_%=;\n\t"
        "WD_%=:\n\t}"
        :: "r"(mbar), "r"(parity) : "memory");
}
__device__ __forceinline__ void bulk_g2s(uint32_t dst, const void* src, uint32_t bytes, uint32_t mbar) {
    asm volatile("cp.async.bulk.shared::cta.global.mbarrier::complete_tx::bytes [%0], [%1], %2, [%3];"
                 :: "r"(dst), "l"(src), "r"(bytes), "r"(mbar) : "memory");
}
__device__ __forceinline__ uint32_t atom_inc_acqrel(uint32_t addr) {
    uint32_t old;
    asm volatile("atom.acq_rel.cta.shared::cta.add.u32 %0, [%1], 1;"
                 : "=r"(old) : "r"(addr) : "memory");
    return old;
}
__device__ __forceinline__ uint4 lds128(uint32_t addr) {
    uint4 v;
    asm volatile("ld.shared.v4.b32 {%0,%1,%2,%3}, [%4];"
                 : "=r"(v.x), "=r"(v.y), "=r"(v.z), "=r"(v.w) : "r"(addr));
    return v;
}
__device__ __forceinline__ void mma16816(float* d, const uint32_t* a, uint32_t b0, uint32_t b1) {
    asm volatile(
        "mma.sync.aligned.m16n8k16.row.col.f32.f16.f16.f32 "
        "{%0,%1,%2,%3}, {%4,%5,%6,%7}, {%8,%9}, {%0,%1,%2,%3};"
        : "+f"(d[0]), "+f"(d[1]), "+f"(d[2]), "+f"(d[3])
        : "r"(a[0]), "r"(a[1]), "r"(a[2]), "r"(a[3]), "r"(b0), "r"(b1));
}
__device__ __forceinline__ uint32_t packh2(float a, float b) {
    __half2 h = __float22half2_rn(make_float2(a, b));
    return *reinterpret_cast<uint32_t*>(&h);
}
__device__ __forceinline__ uint32_t packrelu2(float a, float b) {
    __half2 h = __float22half2_rn(make_float2(a, b));
    h = __hmax2(h, __float2half2_rn(0.f));
    return *reinterpret_cast<uint32_t*>(&h);
}

// ---------------- prep: weights -> fp16 per-lane fragment layout ----------------
__global__ void prep_weights(const float* __restrict__ Ws) {
    int idx = blockIdx.x * blockDim.x + threadIdx.x;
    if (idx >= NLAYER * 64 * 32) return;
    int lane  = idx & 31;
    int e     = (idx >> 5) & 63;   // kt*8 + nt2
    int layer = idx >> 11;
    int kt  = e >> 3;
    int nt2 = e & 7;
    int tig = lane & 3;
    int g   = lane >> 2;
    int k0 = kt * 16 + tig * 2;
    const float* W = Ws + layer * 16384;

    auto pk = [&](int k, int n) -> uint32_t {
        return packh2(W[k * 128 + n], W[(k + 1) * 128 + n]);
    };
    int n0 = nt2 * 16 + g;
    uint4 r;
    r.x = pk(k0,     n0);
    r.y = pk(k0 + 8, n0);
    r.z = pk(k0,     n0 + 8);
    r.w = pk(k0 + 8, n0 + 8);
    *reinterpret_cast<uint4*>(&g_wimg[(size_t)layer * 32768u + (size_t)e * 512u
                                      + (size_t)lane * 16u]) = r;
}

// One mid layer for a 32-row warp tile: A0/A1 -> B0/B1 (reg-pipelined LDS).
__device__ __forceinline__ void mlp_step(
    uint32_t wb, const float* bi,
    uint32_t (&A0)[8][4], uint32_t (&A1)[8][4],
    uint32_t (&B0)[8][4], uint32_t (&B1)[8][4])
{
#pragma unroll
    for (int nt2 = 0; nt2 < 8; nt2++) {
        float2 bb0 = *reinterpret_cast<const float2*>(bi + (2 * nt2) * 8);
        float2 bb1 = *reinterpret_cast<const float2*>(bi + (2 * nt2 + 1) * 8);
        float D[4][4];
        D[0][0] = bb0.x; D[0][1] = bb0.y; D[0][2] = bb0.x; D[0][3] = bb0.y;
        D[1][0] = bb1.x; D[1][1] = bb1.y; D[1][2] = bb1.x; D[1][3] = bb1.y;
        D[2][0] = bb0.x; D[2][1] = bb0.y; D[2][2] = bb0.x; D[2][3] = bb0.y;
        D[3][0] = bb1.x; D[3][1] = bb1.y; D[3][2] = bb1.x; D[3][3] = bb1.y;

        uint4 w = lds128(wb + (uint32_t)(nt2 * 512));
#pragma unroll
        for (int kt = 0; kt < 8; kt++) {
            uint4 wn;
            if (kt < 7) wn = lds128(wb + (uint32_t)(((kt + 1) * 8 + nt2) * 512));
            mma16816(D[0], A0[kt], w.x, w.y);
            mma16816(D[1], A0[kt], w.z, w.w);
            mma16816(D[2], A1[kt], w.x, w.y);
            mma16816(D[3], A1[kt], w.z, w.w);
            if (kt < 7) w = wn;
        }
        B0[nt2][0] = packrelu2(D[0][0], D[0][1]);
        B0[nt2][1] = packrelu2(D[0][2], D[0][3]);
        B0[nt2][2] = packrelu2(D[1][0], D[1][1]);
        B0[nt2][3] = packrelu2(D[1][2], D[1][3]);
        B1[nt2][0] = packrelu2(D[2][0], D[2][1]);
        B1[nt2][1] = packrelu2(D[2][2], D[2][3]);
        B1[nt2][2] = packrelu2(D[3][0], D[3][1]);
        B1[nt2][3] = packrelu2(D[3][2], D[3][3]);
    }
}

// Final hidden layer fused with fc17: returns 4 partial dots.
__device__ __forceinline__ float4 mlp_last(
    uint32_t wb, const float* bi, const float* w7,
    uint32_t (&A0)[8][4], uint32_t (&A1)[8][4])
{
    float s0 = 0.f, s1 = 0.f, s2 = 0.f, s3 = 0.f;
#pragma unroll
    for (int nt2 = 0; nt2 < 8; nt2++) {
        float2 bb0 = *reinterpret_cast<const float2*>(bi + (2 * nt2) * 8);
        float2 bb1 = *reinterpret_cast<const float2*>(bi + (2 * nt2 + 1) * 8);
        float D[4][4];
        D[0][0] = bb0.x; D[0][1] = bb0.y; D[0][2] = bb0.x; D[0][3] = bb0.y;
        D[1][0] = bb1.x; D[1][1] = bb1.y; D[1][2] = bb1.x; D[1][3] = bb1.y;
        D[2][0] = bb0.x; D[2][1] = bb0.y; D[2][2] = bb0.x; D[2][3] = bb0.y;
        D[3][0] = bb1.x; D[3][1] = bb1.y; D[3][2] = bb1.x; D[3][3] = bb1.y;

        uint4 w = lds128(wb + (uint32_t)(nt2 * 512));
#pragma unroll
        for (int kt = 0; kt < 8; kt++) {
            uint4 wn;
            if (kt < 7) wn = lds128(wb + (uint32_t)(((kt + 1) * 8 + nt2) * 512));
            mma16816(D[0], A0[kt], w.x, w.y);
            mma16816(D[1], A0[kt], w.z, w.w);
            mma16816(D[2], A1[kt], w.x, w.y);
            mma16816(D[3], A1[kt], w.z, w.w);
            if (kt < 7) w = wn;
        }
        float2 wa = *reinterpret_cast<const float2*>(w7 + (2 * nt2) * 8);
        float2 wc = *reinterpret_cast<const float2*>(w7 + (2 * nt2 + 1) * 8);
        s0 = fmaf(fmaxf(D[0][0], 0.f), wa.x, fmaf(fmaxf(D[0][1], 0.f), wa.y, s0));
        s1 = fmaf(fmaxf(D[0][2], 0.f), wa.x, fmaf(fmaxf(D[0][3], 0.f), wa.y, s1));
        s0 = fmaf(fmaxf(D[1][0], 0.f), wc.x, fmaf(fmaxf(D[1][1], 0.f), wc.y, s0));
        s1 = fmaf(fmaxf(D[1][2], 0.f), wc.x, fmaf(fmaxf(D[1][3], 0.f), wc.y, s1));
        s2 = fmaf(fmaxf(D[2][0], 0.f), wa.x, fmaf(fmaxf(D[2][1], 0.f), wa.y, s2));
        s3 = fmaf(fmaxf(D[2][2], 0.f), wa.x, fmaf(fmaxf(D[2][3], 0.f), wa.y, s3));
        s2 = fmaf(fmaxf(D[3][0], 0.f), wc.x, fmaf(fmaxf(D[3][1], 0.f), wc.y, s2));
        s3 = fmaf(fmaxf(D[3][2], 0.f), wc.x, fmaf(fmaxf(D[3][3], 0.f), wc.y, s3));
    }
    return make_float4(s0, s1, s2, s3);
}

// ---------------- main fused MLP kernel (persistent CTAs) -------------------
__global__ void __launch_bounds__(256, 1)
mlp_kernel(const float* __restrict__ x, const float* __restrict__ W1,
           const float* __restrict__ b1, const float* __restrict__ bs,
           const float* __restrict__ W17, const float* __restrict__ b17,
           float* __restrict__ out, int ntiles) {
    extern __shared__ __align__(1024) unsigned char smem[];
    uint32_t sb = smem_u32(smem);
    int tid  = threadIdx.x;
    int wid  = tid >> 5;
    int lane = tid & 31;
    int g    = lane >> 2;
    int tig  = lane & 3;

    float* sW1  = reinterpret_cast<float*>(smem + SO_W1);
    float* sB1  = reinterpret_cast<float*>(smem + SO_B1);
    float* sW17 = reinterpret_cast<float*>(smem + SO_W17);
    float* sBias= reinterpret_cast<float*>(smem + SO_BIAS);

    if (tid < NSLOT) mbar_init(sb + SO_FULL + 8u * tid, 1);
    if (tid < 256) sW1[tid] = W1[tid];
    if (tid < 128) { sB1[tid] = b1[tid]; sW17[tid] = W17[tid]; }
    if (tid < 16) reinterpret_cast<uint32_t*>(smem + SO_CNT)[tid] = 0;
    for (int idx = tid; idx < NLAYER * 128; idx += 256) sBias[idx] = bs[idx];
    __syncthreads();

    // total chunk count for THIS CTA: tiles_for_this_cta * NLAYER
    int mytiles = (ntiles - blockIdx.x + gridDim.x - 1) / gridDim.x;
    int lastchunk = mytiles * NLAYER;

    if (tid == 0) {
#pragma unroll
        for (int j = 0; j < NSLOT; j++) {
            if (j < lastchunk) {
                mbar_expect_tx(sb + SO_FULL + 8u * j, 32768);
                bulk_g2s(sb + SO_WBUF + 32768u * j, &g_wimg[(size_t)(j % NLAYER) * 32768u],
                         32768, sb + SO_FULL + 8u * j);
            }
        }
    }

    float b17v = b17[0];
    const float* biasBase = sBias + tig * 2;

    // seed warp-phase stagger once
    if (wid) __nanosleep((unsigned)(wid * 250));

    uint32_t A0[8][4], A1[8][4], B0[8][4], B1[8][4];
    int chunk = 0, slot = 0, phase = 0;   // continuous ring cursor across tiles

    auto ring_advance = [&]() {
        if (lane == 0) {
            uint32_t old = atom_inc_acqrel(sb + SO_CNT + 4u * (uint32_t)(chunk & 15));
            // monotonic counters: counter slot (chunk&15) reused every 16 chunks
            if (old == (uint32_t)((chunk >> 4) * 8 + 7) && chunk + NSLOT < lastchunk) {
                asm volatile("fence.proxy.async.shared::cta;" ::: "memory");
                uint32_t fb = sb + SO_FULL + 8u * (uint32_t)slot;
                mbar_expect_tx(fb, 32768);
                bulk_g2s(sb + SO_WBUF + (uint32_t)slot * 32768u,
                         &g_wimg[(size_t)((chunk + NSLOT) % NLAYER) * 32768u], 32768, fb);
            }
        }
        chunk++;
        if (++slot == NSLOT) { slot = 0; phase ^= 1; }
    };

    for (int tile = blockIdx.x; tile < ntiles; tile += gridDim.x) {
        // ---- fc1: 32 rows per warp -> two m16 fragment sets ----
        size_t p0 = (size_t)tile * 256 + (size_t)(wid * 32 + g);
        float2 xa = reinterpret_cast<const float2*>(x)[p0];
        float2 xb = reinterpret_cast<const float2*>(x)[p0 + 8];
        float2 xc = reinterpret_cast<const float2*>(x)[p0 + 16];
        float2 xd = reinterpret_cast<const float2*>(x)[p0 + 24];

#pragma unroll
        for (int kt = 0; kt < 8; kt++) {
            int c = kt * 16 + tig * 2;
#pragma unroll
            for (int q = 0; q < 2; q++) {
                int cc = c + q * 8;
                float w0 = sW1[cc],     w0y = sW1[128 + cc],     bb0 = sB1[cc];
                float w1 = sW1[cc + 1], w1y = sW1[128 + cc + 1], bb1 = sB1[cc + 1];
                float va0 = fmaf(xa.x, w0, fmaf(xa.y, w0y, bb0));
                float va1 = fmaf(xa.x, w1, fmaf(xa.y, w1y, bb1));
                float vb0 = fmaf(xb.x, w0, fmaf(xb.y, w0y, bb0));
                float vb1 = fmaf(xb.x, w1, fmaf(xb.y, w1y, bb1));
                float vc0 = fmaf(xc.x, w0, fmaf(xc.y, w0y, bb0));
                float vc1 = fmaf(xc.x, w1, fmaf(xc.y, w1y, bb1));
                float vd0 = fmaf(xd.x, w0, fmaf(xd.y, w0y, bb0));
                float vd1 = fmaf(xd.x, w1, fmaf(xd.y, w1y, bb1));
                A0[kt][2 * q]     = packrelu2(va0, va1);
                A0[kt][2 * q + 1] = packrelu2(vb0, vb1);
                A1[kt][2 * q]     = packrelu2(vc0, vc1);
                A1[kt][2 * q + 1] = packrelu2(vd0, vd1);
            }
        }

        // 7 layer pairs with register ping-pong A<->B
#pragma unroll 1
        for (int ii = 0; ii < 7; ii++) {
            {
                mbar_wait(sb + SO_FULL + 8u * (uint32_t)slot, (uint32_t)phase);
                uint32_t wb = sb + SO_WBUF + (uint32_t)slot * 32768u + (uint32_t)lane * 16u;
                mlp_step(wb, biasBase + (2 * ii) * 128, A0, A1, B0, B1);
                ring_advance();
            }
            {
                mbar_wait(sb + SO_FULL + 8u * (uint32_t)slot, (uint32_t)phase);
                uint32_t wb = sb + SO_WBUF + (uint32_t)slot * 32768u + (uint32_t)lane * 16u;
                mlp_step(wb, biasBase + (2 * ii + 1) * 128, B0, B1, A0, A1);
                ring_advance();
            }
        }

        {   // layer 14 + fc17
            mbar_wait(sb + SO_FULL + 8u * (uint32_t)slot, (uint32_t)phase);
            uint32_t wb = sb + SO_WBUF + (uint32_t)slot * 32768u + (uint32_t)lane * 16u;
            float4 s = mlp_last(wb, biasBase + (NLAYER - 1) * 128, sW17 + tig * 2, A0, A1);
            ring_advance();
            float s0 = s.x, s1 = s.y, s2 = s.z, s3 = s.w;
            s0 += __shfl_xor_sync(0xFFFFFFFFu, s0, 1);
            s0 += __shfl_xor_sync(0xFFFFFFFFu, s0, 2);
            s1 += __shfl_xor_sync(0xFFFFFFFFu, s1, 1);
            s1 += __shfl_xor_sync(0xFFFFFFFFu, s1, 2);
            s2 += __shfl_xor_sync(0xFFFFFFFFu, s2, 1);
            s2 += __shfl_xor_sync(0xFFFFFFFFu, s2, 2);
            s3 += __shfl_xor_sync(0xFFFFFFFFu, s3, 1);
            s3 += __shfl_xor_sync(0xFFFFFFFFu, s3, 2);
            if (tig == 0) {
                out[p0]      = s0 + b17v;
                out[p0 + 8]  = s1 + b17v;
                out[p0 + 16] = s2 + b17v;
                out[p0 + 24] = s3 + b17v;
            }
        }
    }
}

// ---------------- launch ----------------
extern "C" void kernel_launch(void* const* d_in, const int* in_sizes, int n_in,
                              void* d_out, int out_size) {
    const float* x   = (const float*)d_in[0];
    const float* W1  = (const float*)d_in[1];
    const float* b1  = (const float*)d_in[2];
    const float* Ws  = (const float*)d_in[3];
    const float* bs  = (const float*)d_in[4];
    const float* W17 = (const float*)d_in[5];
    const float* b17 = (const float*)d_in[6];
    float* out = (float*)d_out;

    cudaFuncSetAttribute(mlp_kernel, cudaFuncAttributeMaxDynamicSharedMemorySize, SMEM_TOTAL);

    int npts = in_sizes[0] / 2;
    int ntiles = npts / 256;

    static int nsm = 0;
    if (nsm == 0) {
        cudaDeviceGetAttribute(&nsm, cudaDevAttrMultiProcessorCount, 0);
        if (nsm <= 0) nsm = 148;
    }
    int nblk = nsm < ntiles ? nsm : ntiles;

    prep_weights<<<(NLAYER * 64 * 32 + 255) / 256, 256>>>(Ws);
    mlp_kernel<<<nblk, 256, SMEM_TOTAL>>>(x, W1, b1, bs, W17, b17, out, ntiles);
}

// round 13
// speedup vs baseline: 11.3595x; 1.0040x over previous
#include <cuda_runtime.h>
#include <cuda_fp16.h>
#include <stdint.h>

#define NLAYER 15
#define NSLOT  6               // ring of 32KB weight slots (layer chunks)

// fp16 fragment-ordered weights: per layer 32KB.
// entry e = kt*8 + nt2: uint4 per lane = (b0 nt 2nt2, b1 nt 2nt2, b0 nt 2nt2+1, b1 nt 2nt2+1)
__device__ __align__(128) unsigned char g_wimg[NLAYER * 32768];

// ---------------- smem layout ----------------
#define SO_FULL   0                    // 6 mbarriers x 8B
#define SO_CNT    64                   // 16 uint32 monotonic chunk counters
#define SO_W1     256                  // 256 floats
#define SO_B1     1280                 // 128 floats
#define SO_W17    1792                 // 128 floats
#define SO_BIAS   2304                 // 15*128 floats
#define SO_WBUF   10240                // 1024-aligned; 6 x 32768 ring
#define SMEM_TOTAL (10240 + NSLOT*32768)   // 206848 B

// ---------------- helpers ----------------
__device__ __forceinline__ uint32_t smem_u32(const void* p) {
    uint32_t a;
    asm("{ .reg .u64 t; cvta.to.shared.u64 t, %1; cvt.u32.u64 %0, t; }" : "=r"(a) : "l"(p));
    return a;
}
__device__ __forceinline__ void mbar_init(uint32_t mbar, uint32_t cnt) {
    asm volatile("mbarrier.init.shared.b64 [%0], %1;" :: "r"(mbar), "r"(cnt) : "memory");
}
__device__ __forceinline__ void mbar_expect_tx(uint32_t mbar, uint32_t bytes) {
    asm volatile("mbarrier.arrive.expect_tx.shared.b64 _, [%0], %1;" :: "r"(mbar), "r"(bytes) : "memory");
}
__device__ __forceinline__ void mbar_wait(uint32_t mbar, uint32_t parity) {
    asm volatile(
        "{\n\t.reg .pred P;\n\t"
        "WL_%=:\n\t"
        "mbarrier.try_wait.parity.acquire.cta.shared::cta.b64 P, [%0], %1, 0x989680;\n\t"
        "@P bra WD_%=;\n\t"
        "bra.uni WL_%=;\n\t"
        "WD_%=:\n\t}"
        :: "r"(mbar), "r"(parity) : "memory");
}
__device__ __forceinline__ void bulk_g2s(uint32_t dst, const void* src, uint32_t bytes, uint32_t mbar) {
    asm volatile("cp.async.bulk.shared::cta.global.mbarrier::complete_tx::bytes [%0], [%1], %2, [%3];"
                 :: "r"(dst), "l"(src), "r"(bytes), "r"(mbar) : "memory");
}
__device__ __forceinline__ uint32_t atom_inc_acqrel(uint32_t addr) {
    uint32_t old;
    asm volatile("atom.acq_rel.cta.shared::cta.add.u32 %0, [%1], 1;"
                 : "=r"(old) : "r"(addr) : "memory");
    return old;
}
__device__ __forceinline__ uint4 lds128(uint32_t addr) {
    uint4 v;
    asm volatile("ld.shared.v4.b32 {%0,%1,%2,%3}, [%4];"
                 : "=r"(v.x), "=r"(v.y), "=r"(v.z), "=r"(v.w) : "r"(addr));
    return v;
}
__device__ __forceinline__ void mma16816(float* d, const uint32_t* a, uint32_t b0, uint32_t b1) {
    asm volatile(
        "mma.sync.aligned.m16n8k16.row.col.f32.f16.f16.f32 "
        "{%0,%1,%2,%3}, {%4,%5,%6,%7}, {%8,%9}, {%0,%1,%2,%3};"
        : "+f"(d[0]), "+f"(d[1]), "+f"(d[2]), "+f"(d[3])
        : "r"(a[0]), "r"(a[1]), "r"(a[2]), "r"(a[3]), "r"(b0), "r"(b1));
}
__device__ __forceinline__ uint32_t packh2(float a, float b) {
    __half2 h = __float22half2_rn(make_float2(a, b));
    return *reinterpret_cast<uint32_t*>(&h);
}
__device__ __forceinline__ uint32_t packrelu2(float a, float b) {
    __half2 h = __float22half2_rn(make_float2(a, b));
    h = __hmax2(h, __float2half2_rn(0.f));
    return *reinterpret_cast<uint32_t*>(&h);
}

// ---------------- prep: weights -> fp16 per-lane fragment layout ----------------
__global__ void prep_weights(const float* __restrict__ Ws) {
    int idx = blockIdx.x * blockDim.x + threadIdx.x;
    if (idx >= NLAYER * 64 * 32) return;
    int lane  = idx & 31;
    int e     = (idx >> 5) & 63;   // kt*8 + nt2
    int layer = idx >> 11;
    int kt  = e >> 3;
    int nt2 = e & 7;
    int tig = lane & 3;
    int g   = lane >> 2;
    int k0 = kt * 16 + tig * 2;
    const float* W = Ws + layer * 16384;

    auto pk = [&](int k, int n) -> uint32_t {
        return packh2(W[k * 128 + n], W[(k + 1) * 128 + n]);
    };
    int n0 = nt2 * 16 + g;
    uint4 r;
    r.x = pk(k0,     n0);
    r.y = pk(k0 + 8, n0);
    r.z = pk(k0,     n0 + 8);
    r.w = pk(k0 + 8, n0 + 8);
    *reinterpret_cast<uint4*>(&g_wimg[(size_t)layer * 32768u + (size_t)e * 512u
                                      + (size_t)lane * 16u]) = r;
}

// One mid layer for a 32-row warp tile: A0/A1 -> B0/B1.
// LDS double-buffer pipelined ACROSS nt2-chunk seams: the kt==7 slot preloads
// chunk nt2+1's kt=0 fragment; next chunk's bias is prefetched mid-chunk.
__device__ __forceinline__ void mlp_step(
    uint32_t wb, const float* bi,
    uint32_t (&A0)[8][4], uint32_t (&A1)[8][4],
    uint32_t (&B0)[8][4], uint32_t (&B1)[8][4])
{
    uint4 w = lds128(wb);                                             // nt2=0, kt=0
    float2 nb0 = *reinterpret_cast<const float2*>(bi);
    float2 nb1 = *reinterpret_cast<const float2*>(bi + 8);
#pragma unroll
    for (int nt2 = 0; nt2 < 8; nt2++) {
        float D[4][4];
        D[0][0] = nb0.x; D[0][1] = nb0.y; D[0][2] = nb0.x; D[0][3] = nb0.y;
        D[1][0] = nb1.x; D[1][1] = nb1.y; D[1][2] = nb1.x; D[1][3] = nb1.y;
        D[2][0] = nb0.x; D[2][1] = nb0.y; D[2][2] = nb0.x; D[2][3] = nb0.y;
        D[3][0] = nb1.x; D[3][1] = nb1.y; D[3][2] = nb1.x; D[3][3] = nb1.y;
        if (nt2 < 7) {
            nb0 = *reinterpret_cast<const float2*>(bi + (2 * nt2 + 2) * 8);
            nb1 = *reinterpret_cast<const float2*>(bi + (2 * nt2 + 3) * 8);
        }
#pragma unroll
        for (int kt = 0; kt < 8; kt++) {
            // next fragment: same chunk kt+1, or next chunk's kt=0 (wrap at end, harmless)
            uint32_t naddr = (kt < 7) ? (uint32_t)(((kt + 1) * 8 + nt2) * 512)
                                      : (uint32_t)(((nt2 + 1) & 7) * 512);
            uint4 wn = lds128(wb + naddr);
            mma16816(D[0], A0[kt], w.x, w.y);
            mma16816(D[1], A0[kt], w.z, w.w);
            mma16816(D[2], A1[kt], w.x, w.y);
            mma16816(D[3], A1[kt], w.z, w.w);
            w = wn;
        }
        B0[nt2][0] = packrelu2(D[0][0], D[0][1]);
        B0[nt2][1] = packrelu2(D[0][2], D[0][3]);
        B0[nt2][2] = packrelu2(D[1][0], D[1][1]);
        B0[nt2][3] = packrelu2(D[1][2], D[1][3]);
        B1[nt2][0] = packrelu2(D[2][0], D[2][1]);
        B1[nt2][1] = packrelu2(D[2][2], D[2][3]);
        B1[nt2][2] = packrelu2(D[3][0], D[3][1]);
        B1[nt2][3] = packrelu2(D[3][2], D[3][3]);
    }
}

// Final hidden layer fused with fc17: returns 4 partial dots.
__device__ __forceinline__ float4 mlp_last(
    uint32_t wb, const float* bi, const float* w7,
    uint32_t (&A0)[8][4], uint32_t (&A1)[8][4])
{
    float s0 = 0.f, s1 = 0.f, s2 = 0.f, s3 = 0.f;
    uint4 w = lds128(wb);
    float2 nb0 = *reinterpret_cast<const float2*>(bi);
    float2 nb1 = *reinterpret_cast<const float2*>(bi + 8);
#pragma unroll
    for (int nt2 = 0; nt2 < 8; nt2++) {
        float D[4][4];
        D[0][0] = nb0.x; D[0][1] = nb0.y; D[0][2] = nb0.x; D[0][3] = nb0.y;
        D[1][0] = nb1.x; D[1][1] = nb1.y; D[1][2] = nb1.x; D[1][3] = nb1.y;
        D[2][0] = nb0.x; D[2][1] = nb0.y; D[2][2] = nb0.x; D[2][3] = nb0.y;
        D[3][0] = nb1.x; D[3][1] = nb1.y; D[3][2] = nb1.x; D[3][3] = nb1.y;
        if (nt2 < 7) {
            nb0 = *reinterpret_cast<const float2*>(bi + (2 * nt2 + 2) * 8);
            nb1 = *reinterpret_cast<const float2*>(bi + (2 * nt2 + 3) * 8);
        }
#pragma unroll
        for (int kt = 0; kt < 8; kt++) {
            uint32_t naddr = (kt < 7) ? (uint32_t)(((kt + 1) * 8 + nt2) * 512)
                                      : (uint32_t)(((nt2 + 1) & 7) * 512);
            uint4 wn = lds128(wb + naddr);
            mma16816(D[0], A0[kt], w.x, w.y);
            mma16816(D[1], A0[kt], w.z, w.w);
            mma16816(D[2], A1[kt], w.x, w.y);
            mma16816(D[3], A1[kt], w.z, w.w);
            w = wn;
        }
        float2 wa = *reinterpret_cast<const float2*>(w7 + (2 * nt2) * 8);
        float2 wc = *reinterpret_cast<const float2*>(w7 + (2 * nt2 + 1) * 8);
        s0 = fmaf(fmaxf(D[0][0], 0.f), wa.x, fmaf(fmaxf(D[0][1], 0.f), wa.y, s0));
        s1 = fmaf(fmaxf(D[0][2], 0.f), wa.x, fmaf(fmaxf(D[0][3], 0.f), wa.y, s1));
        s0 = fmaf(fmaxf(D[1][0], 0.f), wc.x, fmaf(fmaxf(D[1][1], 0.f), wc.y, s0));
        s1 = fmaf(fmaxf(D[1][2], 0.f), wc.x, fmaf(fmaxf(D[1][3], 0.f), wc.y, s1));
        s2 = fmaf(fmaxf(D[2][0], 0.f), wa.x, fmaf(fmaxf(D[2][1], 0.f), wa.y, s2));
        s3 = fmaf(fmaxf(D[2][2], 0.f), wa.x, fmaf(fmaxf(D[2][3], 0.f), wa.y, s3));
        s2 = fmaf(fmaxf(D[3][0], 0.f), wc.x, fmaf(fmaxf(D[3][1], 0.f), wc.y, s2));
        s3 = fmaf(fmaxf(D[3][2], 0.f), wc.x, fmaf(fmaxf(D[3][3], 0.f), wc.y, s3));
    }
    return make_float4(s0, s1, s2, s3);
}

// ---------------- main fused MLP kernel (persistent CTAs) -------------------
__global__ void __launch_bounds__(256, 1)
mlp_kernel(const float* __restrict__ x, const float* __restrict__ W1,
           const float* __restrict__ b1, const float* __restrict__ bs,
           const float* __restrict__ W17, const float* __restrict__ b17,
           float* __restrict__ out, int ntiles) {
    extern __shared__ __align__(1024) unsigned char smem[];
    uint32_t sb = smem_u32(smem);
    int tid  = threadIdx.x;
    int wid  = tid >> 5;
    int lane = tid & 31;
    int g    = lane >> 2;
    int tig  = lane & 3;

    float* sW1  = reinterpret_cast<float*>(smem + SO_W1);
    float* sB1  = reinterpret_cast<float*>(smem + SO_B1);
    float* sW17 = reinterpret_cast<float*>(smem + SO_W17);
    float* sBias= reinterpret_cast<float*>(smem + SO_BIAS);

    if (tid < NSLOT) mbar_init(sb + SO_FULL + 8u * tid, 1);
    if (tid < 256) sW1[tid] = W1[tid];
    if (tid < 128) { sB1[tid] = b1[tid]; sW17[tid] = W17[tid]; }
    if (tid < 16) reinterpret_cast<uint32_t*>(smem + SO_CNT)[tid] = 0;
    for (int idx = tid; idx < NLAYER * 128; idx += 256) sBias[idx] = bs[idx];
    __syncthreads();

    int mytiles = (ntiles - blockIdx.x + gridDim.x - 1) / gridDim.x;
    int lastchunk = mytiles * NLAYER;

    if (tid == 0) {
#pragma unroll
        for (int j = 0; j < NSLOT; j++) {
            if (j < lastchunk) {
                mbar_expect_tx(sb + SO_FULL + 8u * j, 32768);
                bulk_g2s(sb + SO_WBUF + 32768u * j, &g_wimg[(size_t)(j % NLAYER) * 32768u],
                         32768, sb + SO_FULL + 8u * j);
            }
        }
    }

    float b17v = b17[0];
    const float* biasBase = sBias + tig * 2;

    if (wid) __nanosleep((unsigned)(wid * 250));

    uint32_t A0[8][4], A1[8][4], B0[8][4], B1[8][4];
    int chunk = 0, slot = 0, phase = 0;

    auto ring_advance = [&]() {
        if (lane == 0) {
            uint32_t old = atom_inc_acqrel(sb + SO_CNT + 4u * (uint32_t)(chunk & 15));
            if (old == (uint32_t)((chunk >> 4) * 8 + 7) && chunk + NSLOT < lastchunk) {
                asm volatile("fence.proxy.async.shared::cta;" ::: "memory");
                uint32_t fb = sb + SO_FULL + 8u * (uint32_t)slot;
                mbar_expect_tx(fb, 32768);
                bulk_g2s(sb + SO_WBUF + (uint32_t)slot * 32768u,
                         &g_wimg[(size_t)((chunk + NSLOT) % NLAYER) * 32768u], 32768, fb);
            }
        }
        chunk++;
        if (++slot == NSLOT) { slot = 0; phase ^= 1; }
    };

    for (int tile = blockIdx.x; tile < ntiles; tile += gridDim.x) {
        // ---- fc1: 32 rows per warp -> two m16 fragment sets ----
        size_t p0 = (size_t)tile * 256 + (size_t)(wid * 32 + g);
        float2 xa = reinterpret_cast<const float2*>(x)[p0];
        float2 xb = reinterpret_cast<const float2*>(x)[p0 + 8];
        float2 xc = reinterpret_cast<const float2*>(x)[p0 + 16];
        float2 xd = reinterpret_cast<const float2*>(x)[p0 + 24];

#pragma unroll
        for (int kt = 0; kt < 8; kt++) {
            int c = kt * 16 + tig * 2;
#pragma unroll
            for (int q = 0; q < 2; q++) {
                int cc = c + q * 8;
                float w0 = sW1[cc],     w0y = sW1[128 + cc],     bb0 = sB1[cc];
                float w1 = sW1[cc + 1], w1y = sW1[128 + cc + 1], bb1 = sB1[cc + 1];
                float va0 = fmaf(xa.x, w0, fmaf(xa.y, w0y, bb0));
                float va1 = fmaf(xa.x, w1, fmaf(xa.y, w1y, bb1));
                float vb0 = fmaf(xb.x, w0, fmaf(xb.y, w0y, bb0));
                float vb1 = fmaf(xb.x, w1, fmaf(xb.y, w1y, bb1));
                float vc0 = fmaf(xc.x, w0, fmaf(xc.y, w0y, bb0));
                float vc1 = fmaf(xc.x, w1, fmaf(xc.y, w1y, bb1));
                float vd0 = fmaf(xd.x, w0, fmaf(xd.y, w0y, bb0));
                float vd1 = fmaf(xd.x, w1, fmaf(xd.y, w1y, bb1));
                A0[kt][2 * q]     = packrelu2(va0, va1);
                A0[kt][2 * q + 1] = packrelu2(vb0, vb1);
                A1[kt][2 * q]     = packrelu2(vc0, vc1);
                A1[kt][2 * q + 1] = packrelu2(vd0, vd1);
            }
        }

        // 7 layer pairs with register ping-pong A<->B
#pragma unroll 1
        for (int ii = 0; ii < 7; ii++) {
            {
                mbar_wait(sb + SO_FULL + 8u * (uint32_t)slot, (uint32_t)phase);
                uint32_t wb = sb + SO_WBUF + (uint32_t)slot * 32768u + (uint32_t)lane * 16u;
                mlp_step(wb, biasBase + (2 * ii) * 128, A0, A1, B0, B1);
                ring_advance();
            }
            {
                mbar_wait(sb + SO_FULL + 8u * (uint32_t)slot, (uint32_t)phase);
                uint32_t wb = sb + SO_WBUF + (uint32_t)slot * 32768u + (uint32_t)lane * 16u;
                mlp_step(wb, biasBase + (2 * ii + 1) * 128, B0, B1, A0, A1);
                ring_advance();
            }
        }

        {   // layer 14 + fc17
            mbar_wait(sb + SO_FULL + 8u * (uint32_t)slot, (uint32_t)phase);
            uint32_t wb = sb + SO_WBUF + (uint32_t)slot * 32768u + (uint32_t)lane * 16u;
            float4 s = mlp_last(wb, biasBase + (NLAYER - 1) * 128, sW17 + tig * 2, A0, A1);
            ring_advance();
            float s0 = s.x, s1 = s.y, s2 = s.z, s3 = s.w;
            s0 += __shfl_xor_sync(0xFFFFFFFFu, s0, 1);
            s0 += __shfl_xor_sync(0xFFFFFFFFu, s0, 2);
            s1 += __shfl_xor_sync(0xFFFFFFFFu, s1, 1);
            s1 += __shfl_xor_sync(0xFFFFFFFFu, s1, 2);
            s2 += __shfl_xor_sync(0xFFFFFFFFu, s2, 1);
            s2 += __shfl_xor_sync(0xFFFFFFFFu, s2, 2);
            s3 += __shfl_xor_sync(0xFFFFFFFFu, s3, 1);
            s3 += __shfl_xor_sync(0xFFFFFFFFu, s3, 2);
            if (tig == 0) {
                out[p0]      = s0 + b17v;
                out[p0 + 8]  = s1 + b17v;
                out[p0 + 16] = s2 + b17v;
                out[p0 + 24] = s3 + b17v;
            }
        }
    }
}

// ---------------- launch ----------------
extern "C" void kernel_launch(void* const* d_in, const int* in_sizes, int n_in,
                              void* d_out, int out_size) {
    const float* x   = (const float*)d_in[0];
    const float* W1  = (const float*)d_in[1];
    const float* b1  = (const float*)d_in[2];
    const float* Ws  = (const float*)d_in[3];
    const float* bs  = (const float*)d_in[4];
    const float* W17 = (const float*)d_in[5];
    const float* b17 = (const float*)d_in[6];
    float* out = (float*)d_out;

    cudaFuncSetAttribute(mlp_kernel, cudaFuncAttributeMaxDynamicSharedMemorySize, SMEM_TOTAL);

    int npts = in_sizes[0] / 2;
    int ntiles = npts / 256;

    static int nsm = 0;
    if (nsm == 0) {
        cudaDeviceGetAttribute(&nsm, cudaDevAttrMultiProcessorCount, 0);
        if (nsm <= 0) nsm = 148;
    }
    int nblk = nsm < ntiles ? nsm : ntiles;

    prep_weights<<<(NLAYER * 64 * 32 + 255) / 256, 256>>>(Ws);
    mlp_kernel<<<nblk, 256, SMEM_TOTAL>>>(x, W1, b1, bs, W17, b17, out, ntiles);
}